// round 13
// baseline (speedup 1.0000x reference)
#include <cuda_runtime.h>
#include <cuda_fp16.h>
#include <cstdint>

#define NLOC 6400
#define DH   144
#define VROWS 160            // 144 dh + ones row (144) + 15 zero rows
#define NPIX 25600
#define CIN  64
#define CI   16
#define DD   8
#define MIDOFF (4*NPIX)

// ---------------- gmem scratch ----------------
__device__ float  g_X[2*3*CI*NPIX];
__device__ __half g_Qh[2*NLOC*DH + 32*DH];   // fp16, pre-scaled by 10*log2(e); padded for last-CTA overread
__device__ __half g_Kf[2*NLOC*DH];           // fp16 [loc][dh]
__device__ __half g_Vt[2*VROWS*NLOC];        // fp16 transposed [dh][loc], rows 144..159 = ones/zeros
__device__ float  g_Z[2*NLOC*DH];

// ---------------- helpers ----------------
__device__ __forceinline__ uint32_t smem_u32(const void* p){
    uint32_t a; asm("{ .reg .u64 t; cvta.to.shared.u64 t, %1; cvt.u32.u64 %0, t; }" : "=r"(a) : "l"(p));
    return a;
}
__device__ __forceinline__ float ex2(float x){
    float y; asm("ex2.approx.ftz.f32 %0, %1;" : "=f"(y) : "f"(x)); return y;
}
// pack two fp32 -> fp16x2, lo half = first arg
__device__ __forceinline__ uint32_t pkh(float lo, float hi){
    uint32_t u; asm("cvt.rn.f16x2.f32 %0, %1, %2;" : "=r"(u) : "f"(hi), "f"(lo)); return u;
}
__device__ __forceinline__ uint32_t h2ex2(uint32_t x){
    uint32_t y; asm("ex2.approx.f16x2 %0, %1;" : "=r"(y) : "r"(x)); return y;
}
__device__ __forceinline__ void mma16816(float* d, const uint32_t* a, const uint32_t* b, const float* c){
    asm volatile("mma.sync.aligned.m16n8k16.row.col.f32.f16.f16.f32 "
        "{%0,%1,%2,%3}, {%4,%5,%6,%7}, {%8,%9}, {%10,%11,%12,%13};"
        : "=f"(d[0]),"=f"(d[1]),"=f"(d[2]),"=f"(d[3])
        : "r"(a[0]),"r"(a[1]),"r"(a[2]),"r"(a[3]), "r"(b[0]),"r"(b[1]),
          "f"(c[0]),"f"(c[1]),"f"(c[2]),"f"(c[3]));
}
__device__ __forceinline__ void ldsm4(uint32_t* r, uint32_t addr){
    asm volatile("ldmatrix.sync.aligned.m8n8.x4.shared.b16 {%0,%1,%2,%3}, [%4];"
        : "=r"(r[0]),"=r"(r[1]),"=r"(r[2]),"=r"(r[3]) : "r"(addr));
}
__device__ __forceinline__ void cpa(uint32_t dst, const void* src){
    asm volatile("cp.async.cg.shared.global [%0], [%1], 16;" :: "r"(dst), "l"(src));
}
__device__ __forceinline__ void cp_commit(){ asm volatile("cp.async.commit_group;" ::: "memory"); }
template<int N> __device__ __forceinline__ void cp_wait(){ asm volatile("cp.async.wait_group %0;" :: "n"(N) : "memory"); }

// ================= K1: 1x1 conv at mid slice =================
__global__ void conv_mid_kernel(const float* __restrict__ b,
                                const float* __restrict__ gw, const float* __restrict__ gb,
                                const float* __restrict__ tw, const float* __restrict__ tb,
                                const float* __restrict__ pw, const float* __restrict__ pb)
{
    __shared__ float ws[3*CI*CIN];
    __shared__ float bs[3*CI];
    int tid = threadIdx.x;
    for (int i = tid; i < CI*CIN; i += 256){
        ws[i] = gw[i]; ws[CI*CIN + i] = tw[i]; ws[2*CI*CIN + i] = pw[i];
    }
    if (tid < CI){ bs[tid] = gb[tid]; bs[CI+tid] = tb[tid]; bs[2*CI+tid] = pb[tid]; }
    __syncthreads();

    int pix = blockIdx.x*256 + tid;
    int batch = blockIdx.y;
    const float* bp = b + (size_t)batch*CIN*DD*NPIX + MIDOFF + pix;
    float acc[48];
    #pragma unroll
    for (int i = 0; i < 48; i++) acc[i] = bs[i];
    for (int c = 0; c < CIN; c++){
        float v = bp[(size_t)c*DD*NPIX];
        #pragma unroll
        for (int m = 0; m < 3; m++)
            #pragma unroll
            for (int ci = 0; ci < CI; ci++)
                acc[m*CI + ci] += ws[m*CI*CIN + ci*CIN + c] * v;
    }
    float* xo = g_X + (size_t)batch*3*CI*NPIX;
    #pragma unroll
    for (int i = 0; i < 48; i++) xo[(size_t)i*NPIX + pix] = acc[i];
}

// ================= K2a: init ones/zero rows of Vt =================
__global__ void vinit_kernel()
{
    int i = blockIdx.x*256 + threadIdx.x;     // 2*16*6400 = 204800
    int batch = i / (16*NLOC);
    int rem = i - batch*(16*NLOC);
    int r = rem / NLOC;
    int c = rem - r*NLOC;
    g_Vt[(size_t)batch*VROWS*NLOC + (size_t)(144 + r)*NLOC + c] =
        (r == 0) ? __float2half(1.f) : __float2half(0.f);
}

// ================= K2: unfold -> Qh(fp16 scaled), Kf(fp16), Vt(fp16 transposed) ===
__global__ void build_patches_kernel()
{
    int batch = blockIdx.z;
    int mat   = blockIdx.y;                    // 0=g->Q, 1=theta->V, 2=phi->K
    int idx   = blockIdx.x*256 + threadIdx.x;  // 921600
    int l, j;
    if (mat == 1){ j = idx / NLOC; l = idx - j*NLOC; }
    else         { l = idx / DH;   j = idx - l*DH;  }
    int ci = j/9, t = j%9, kr = t/3, kc = t%3;
    int ih = l/80, iw = l%80;
    int r = ih*2 + kr - 1, c = iw*2 + kc - 1;
    const float* X = g_X + ((size_t)(batch*3 + mat))*CI*NPIX;
    float v = 0.f;
    if ((unsigned)r < 160u && (unsigned)c < 160u) v = X[ci*NPIX + r*160 + c];

    if (mat == 0){
        g_Qh[(size_t)batch*NLOC*DH + idx] = __float2half_rn(v * 14.4269504088896340736f);
    } else if (mat == 1){
        g_Vt[(size_t)batch*VROWS*NLOC + idx] = __float2half_rn(v);
    } else {
        g_Kf[(size_t)batch*NLOC*DH + idx] = __float2half_rn(v);
    }
}

// ================= K3: flash attention, mma.sync (HMMA), 12 warps/key-split ======
#define BM   96
#define QSTR 152              // halves per Q-tile row (304B, conflict-free ldsm)
#define KSTR 152              // halves per K-tile row
#define VSTR 72               // halves per V-tile row (144B)
#define QTB  (96*QSTR*2)      // 29184 bytes
#define KTB  (64*KSTR*2)      // 19456 bytes
#define VTB  (VROWS*VSTR*2)   // 23040 bytes
#define BUFB (KTB+VTB)        // 42496
#define SMB_FLASH (QTB + 3*BUFB)  // 156672
#define NTH  384

__device__ __forceinline__ void load_tiles(uint32_t ring, int buf,
                                           const __half* Kg, const __half* Vg,
                                           int kb, int tid)
{
    uint32_t kd = ring + buf*BUFB;
    const __half* ks = Kg + (size_t)kb*64*DH;
    #pragma unroll
    for (int j = 0; j < 3; j++){
        int id = tid + j*NTH;             // 64 rows x 18 chunks(16B) = 1152
        int r = id/18, c = id - r*18;
        cpa(kd + r*(KSTR*2) + c*16, ks + r*DH + c*8);
    }
    uint32_t vd = ring + buf*BUFB + KTB;
    const __half* vs = Vg + kb*64;
    #pragma unroll
    for (int j = 0; j < 4; j++){
        int id = tid + j*NTH;             // 160 rows x 8 chunks(16B) = 1280
        if (id < 1280){
            int r = id>>3, c = id&7;
            cpa(vd + r*(VSTR*2) + c*16, vs + (size_t)r*NLOC + c*8);
        }
    }
}

__global__ __launch_bounds__(NTH, 1) void flash_kernel()
{
    extern __shared__ char sm[];
    uint32_t smb = smem_u32(sm);
    const uint32_t ring = smb + QTB;
    const int tid = threadIdx.x, w = tid>>5, lane = tid&31;
    const int g = lane>>2, tig = lane&3;
    const int wp = w>>1;                 // row group 0..5
    const int hf = w&1;                  // key half 0/1
    const int qb = blockIdx.x, batch = blockIdx.y;

    const __half* Qg = g_Qh + (size_t)batch*NLOC*DH;
    const __half* Kg = g_Kf + (size_t)batch*NLOC*DH;
    const __half* Vg = g_Vt + (size_t)batch*VROWS*NLOC;
    float*        Zg = g_Z  + (size_t)batch*NLOC*DH;

    // ---- Q tile -> smem via cp.async (96 rows x 18 chunks = 1728) ----
    {
        const __half* qs = Qg + (size_t)qb*BM*DH;
        #pragma unroll
        for (int j = 0; j < 5; j++){
            int id = tid + j*NTH;
            if (id < 1728){
                int r = id/18, c = id - r*18;
                cpa(smb + r*(QSTR*2) + c*16, qs + r*DH + c*8);
            }
        }
        cp_commit();
    }

    // ldmatrix per-lane base offsets (B operand: K / V tiles)
    const int lm = lane>>3;
    const int lr = lane&7;
    const int lrow = lr + ((lm&2)<<2);
    const int lcol = (lm&1)*16;
    // A operand (Q tile): m0=(r0-7,c0-7) m1=(r8-15,c0-7) m2=(r0-7,c8-15) m3=(r8-15,c8-15)
    const uint32_t qmb = smb + (uint32_t)(wp*16 + lr + ((lm&1)<<3))*(QSTR*2) + ((lm>>1)<<4);

    // oa[0..17]: O (144 dh). oa[18]: l column (col 144 live). Partial over key half.
    float oa[19][4];
    #pragma unroll
    for (int j = 0; j < 19; j++){ oa[j][0]=0.f; oa[j][1]=0.f; oa[j][2]=0.f; oa[j][3]=0.f; }
    float m0 = -1e30f, m1 = -1e30f;     // per-warp running max over OWN key half

    load_tiles(ring, 0, Kg, Vg, 0, tid); cp_commit();
    load_tiles(ring, 1, Kg, Vg, 1, tid); cp_commit();

    const int row0 = qb*BM + wp*16 + g;

    for (int t = 0; t < 100; t++){
        if (t + 2 < 100) cp_wait<1>(); else cp_wait<0>();
        __syncthreads();
        if (t+2 < 100){ load_tiles(ring, (t+2)%3, Kg, Vg, t+2, tid); cp_commit(); }

        const uint32_t kmb = ring + (t%3)*BUFB + (hf*32 + lrow)*(KSTR*2) + lcol;
        const uint32_t vmb = ring + (t%3)*BUFB + KTB + lrow*(VSTR*2) + lcol + hf*64;

        // ---- S = Q*K over this warp's 32 keys (A from smem) ----
        float sa[4][4];
        #pragma unroll
        for (int j = 0; j < 4; j++){ sa[j][0]=0.f; sa[j][1]=0.f; sa[j][2]=0.f; sa[j][3]=0.f; }
        #pragma unroll
        for (int kt = 0; kt < 9; kt++){
            uint32_t qa[4];
            ldsm4(qa, qmb + kt*32);
            uint32_t bb[2][4];
            ldsm4(bb[0], kmb + kt*32);
            ldsm4(bb[1], kmb + 16*(KSTR*2) + kt*32);
            mma16816(sa[0], qa, bb[0],   sa[0]);
            mma16816(sa[1], qa, bb[0]+2, sa[1]);
            mma16816(sa[2], qa, bb[1],   sa[2]);
            mma16816(sa[3], qa, bb[1]+2, sa[3]);
        }

        // ---- local max (per-warp, independent) ----
        float mx0 = fmaxf(fmaxf(sa[0][0], sa[0][1]), fmaxf(sa[1][0], sa[1][1]));
        float mx1 = fmaxf(fmaxf(sa[0][2], sa[0][3]), fmaxf(sa[1][2], sa[1][3]));
        mx0 = fmaxf(mx0, fmaxf(fmaxf(sa[2][0], sa[2][1]), fmaxf(sa[3][0], sa[3][1])));
        mx1 = fmaxf(mx1, fmaxf(fmaxf(sa[2][2], sa[2][3]), fmaxf(sa[3][2], sa[3][3])));

        if (!__all_sync(0xffffffffu, (mx0 <= m0) && (mx1 <= m1))){
            mx0 = fmaxf(mx0, __shfl_xor_sync(0xffffffffu, mx0, 1));
            mx0 = fmaxf(mx0, __shfl_xor_sync(0xffffffffu, mx0, 2));
            mx1 = fmaxf(mx1, __shfl_xor_sync(0xffffffffu, mx1, 1));
            mx1 = fmaxf(mx1, __shfl_xor_sync(0xffffffffu, mx1, 2));
            float m0n = fmaxf(m0, mx0), m1n = fmaxf(m1, mx1);
            float sc0 = ex2(m0 - m0n),  sc1 = ex2(m1 - m1n);
            m0 = m0n; m1 = m1n;
            #pragma unroll
            for (int j = 0; j < 19; j++){
                oa[j][0] *= sc0; oa[j][1] *= sc0;
                oa[j][2] *= sc1; oa[j][3] *= sc1;
            }
        }

        // ---- P fragments via fp16x2 exp2 ----
        uint32_t pa[2][4];
        #pragma unroll
        for (int k2 = 0; k2 < 2; k2++){
            pa[k2][0] = h2ex2(pkh(sa[2*k2][0]  - m0, sa[2*k2][1]  - m0));
            pa[k2][1] = h2ex2(pkh(sa[2*k2][2]  - m1, sa[2*k2][3]  - m1));
            pa[k2][2] = h2ex2(pkh(sa[2*k2+1][0]- m0, sa[2*k2+1][1]- m0));
            pa[k2][3] = h2ex2(pkh(sa[2*k2+1][2]- m1, sa[2*k2+1][3]- m1));
        }

        // ---- O += P * V over this warp's 32 keys (9 dh blocks + l block) ----
        #pragma unroll
        for (int k2 = 0; k2 < 2; k2++){
            #pragma unroll
            for (int np = 0; np < 9; np++){
                uint32_t bb[4];
                ldsm4(bb, vmb + np*16*(VSTR*2) + k2*32);
                mma16816(oa[2*np],   pa[k2], bb,   oa[2*np]);
                mma16816(oa[2*np+1], pa[k2], bb+2, oa[2*np+1]);
            }
            uint32_t bb[4];
            ldsm4(bb, vmb + 9*16*(VSTR*2) + k2*32);
            mma16816(oa[18], pa[k2], bb, oa[18]);
        }
    }

    // ================= merge warp pairs (odd -> smem, even combines) =============
    __syncthreads();                      // tile reads done; reuse smem
    float4* xO = (float4*)sm;             // [6 wp][32 lanes][20 f4]
    float*  xM = (float*)(sm + 61440);    // [6 wp][32 lanes][2]
    if (hf){
        float4* dst = xO + (size_t)wp*640 + lane*20;
        #pragma unroll
        for (int j = 0; j < 19; j++)
            dst[j] = make_float4(oa[j][0], oa[j][1], oa[j][2], oa[j][3]);
        float* mm = xM + wp*64 + lane*2;
        mm[0] = m0; mm[1] = m1;
    }
    __syncthreads();
    if (!hf){
        const float4* src = xO + (size_t)wp*640 + lane*20;
        const float* mm = xM + wp*64 + lane*2;
        float pm0 = mm[0], pm1 = mm[1];
        float ms0 = fmaxf(m0, pm0), ms1 = fmaxf(m1, pm1);
        float sA0 = ex2(m0 - ms0), sB0 = ex2(pm0 - ms0);
        float sA1 = ex2(m1 - ms1), sB1 = ex2(pm1 - ms1);
        #pragma unroll
        for (int j = 0; j < 19; j++){
            float4 p = src[j];
            oa[j][0] = oa[j][0]*sA0 + p.x*sB0;
            oa[j][1] = oa[j][1]*sA0 + p.y*sB0;
            oa[j][2] = oa[j][2]*sA1 + p.z*sB1;
            oa[j][3] = oa[j][3]*sA1 + p.w*sB1;
        }
        float l0 = __shfl_sync(0xffffffffu, oa[18][0], lane & 28);
        float l1 = __shfl_sync(0xffffffffu, oa[18][2], lane & 28);
        float i0 = 1.f/l0, i1 = 1.f/l1;
        if (row0 < NLOC){
            float* z = Zg + (size_t)row0*DH + tig*2;
            #pragma unroll
            for (int j = 0; j < 18; j++)
                *(float2*)(z + j*8) = make_float2(oa[j][0]*i0, oa[j][1]*i0);
        }
        if (row0 + 8 < NLOC){
            float* z = Zg + (size_t)(row0+8)*DH + tig*2;
            #pragma unroll
            for (int j = 0; j < 18; j++)
                *(float2*)(z + j*8) = make_float2(oa[j][2]*i1, oa[j][3]*i1);
        }
    }
}

// ================= K4: fused fold + W conv + residual add (split over c-halves) ==
__global__ void fold_w_out_kernel(const float* __restrict__ Ww, const float* __restrict__ Wb,
                                  const float* __restrict__ bin, float* __restrict__ out)
{
    __shared__ float ws[32*CI];
    __shared__ float wb[32];
    int tid = threadIdx.x;
    int c0 = blockIdx.z*32;
    for (int i = tid; i < 32*CI; i += 256) ws[i] = Ww[c0*CI + i];
    if (tid < 32) wb[tid] = Wb[c0 + tid];
    __syncthreads();

    int pix = blockIdx.x*256 + tid;
    int batch = blockIdx.y;
    int h = pix / 160, w = pix % 160;

    int krs[2], ihs[2], nr = 0;
    if (!(h & 1)){ krs[0] = 1; ihs[0] = h >> 1; nr = 1; }
    else { if (h < 159){ krs[nr] = 0; ihs[nr] = (h+1) >> 1; nr++; } krs[nr] = 2; ihs[nr] = (h-1) >> 1; nr++; }
    int kcs[2], iws[2], nc = 0;
    if (!(w & 1)){ kcs[0] = 1; iws[0] = w >> 1; nc = 1; }
    else { if (w < 159){ kcs[nc] = 0; iws[nc] = (w+1) >> 1; nc++; } kcs[nc] = 2; iws[nc] = (w-1) >> 1; nc++; }

    const float* Z = g_Z + (size_t)batch*NLOC*DH;
    float acc[CI];
    #pragma unroll
    for (int ci = 0; ci < CI; ci++) acc[ci] = 0.f;
    for (int a = 0; a < nr; a++)
        for (int bb = 0; bb < nc; bb++){
            int l = ihs[a]*80 + iws[bb];
            const float* zp = Z + (size_t)l*DH + krs[a]*3 + kcs[bb];
            #pragma unroll
            for (int ci = 0; ci < CI; ci++) acc[ci] += zp[ci*9];
        }
    float inv = 1.f / (float)(nr*nc);
    #pragma unroll
    for (int ci = 0; ci < CI; ci++) acc[ci] *= inv;

    const float* bp = bin + (size_t)batch*CIN*DD*NPIX + (size_t)c0*DD*NPIX + pix;
    float*       op = out + (size_t)batch*CIN*DD*NPIX + (size_t)c0*DD*NPIX + pix;
    #pragma unroll 2
    for (int c = 0; c < 32; c++){
        float y = wb[c];
        #pragma unroll
        for (int ci = 0; ci < CI; ci++) y += ws[c*CI + ci]*acc[ci];
        const float* bc = bp + (size_t)c*DD*NPIX;
        float*       oc = op + (size_t)c*DD*NPIX;
        #pragma unroll
        for (int d = 0; d < DD; d++)
            oc[(size_t)d*NPIX] = bc[(size_t)d*NPIX] + y;
    }
}

// ================= launch =================
extern "C" void kernel_launch(void* const* d_in, const int* in_sizes, int n_in,
                              void* d_out, int out_size)
{
    const float* b  = (const float*)d_in[0];
    const float* gw = (const float*)d_in[1];
    const float* gb = (const float*)d_in[2];
    const float* tw = (const float*)d_in[3];
    const float* tb = (const float*)d_in[4];
    const float* pw = (const float*)d_in[5];
    const float* pb = (const float*)d_in[6];
    const float* Ww = (const float*)d_in[7];
    const float* Wb = (const float*)d_in[8];
    float* out = (float*)d_out;

    cudaFuncSetAttribute(flash_kernel, cudaFuncAttributeMaxDynamicSharedMemorySize, SMB_FLASH);

    conv_mid_kernel<<<dim3(100, 2), 256>>>(b, gw, gb, tw, tb, pw, pb);
    vinit_kernel<<<800, 256>>>();
    build_patches_kernel<<<dim3(3600, 3, 2), 256>>>();
    flash_kernel<<<dim3(67, 2), NTH, SMB_FLASH>>>();
    fold_w_out_kernel<<<dim3(100, 2, 2), 256>>>(Ww, Wb, b, out);
}

// round 14
// speedup vs baseline: 1.0068x; 1.0068x over previous
#include <cuda_runtime.h>
#include <cuda_fp16.h>
#include <cstdint>

#define NLOC 6400
#define DH   144
#define VROWS 160            // 144 dh + ones row (144) + 15 zero rows
#define NPIX 25600
#define CIN  64
#define CI   16
#define DD   8
#define MIDOFF (4*NPIX)

// ---------------- gmem scratch ----------------
__device__ float  g_X[2*3*CI*NPIX];
__device__ __half g_Qh[2*NLOC*DH + 32*DH];   // fp16, pre-scaled by 10*log2(e); padded
__device__ __half g_Kf[2*NLOC*DH];           // fp16 [loc][dh]
__device__ __half g_Vt[2*VROWS*NLOC];        // fp16 transposed [dh][loc], rows 144..159 = ones/zeros
__device__ __half g_Zh[2*NLOC*DH];           // fp16 attention output

// ---------------- helpers ----------------
__device__ __forceinline__ uint32_t smem_u32(const void* p){
    uint32_t a; asm("{ .reg .u64 t; cvta.to.shared.u64 t, %1; cvt.u32.u64 %0, t; }" : "=r"(a) : "l"(p));
    return a;
}
__device__ __forceinline__ float ex2(float x){
    float y; asm("ex2.approx.ftz.f32 %0, %1;" : "=f"(y) : "f"(x)); return y;
}
// pack two fp32 -> fp16x2, lo half = first arg
__device__ __forceinline__ uint32_t pkh(float lo, float hi){
    uint32_t u; asm("cvt.rn.f16x2.f32 %0, %1, %2;" : "=r"(u) : "f"(hi), "f"(lo)); return u;
}
__device__ __forceinline__ uint32_t h2ex2(uint32_t x){
    uint32_t y; asm("ex2.approx.f16x2 %0, %1;" : "=r"(y) : "r"(x)); return y;
}
__device__ __forceinline__ void mma16816(float* d, const uint32_t* a, const uint32_t* b, const float* c){
    asm volatile("mma.sync.aligned.m16n8k16.row.col.f32.f16.f16.f32 "
        "{%0,%1,%2,%3}, {%4,%5,%6,%7}, {%8,%9}, {%10,%11,%12,%13};"
        : "=f"(d[0]),"=f"(d[1]),"=f"(d[2]),"=f"(d[3])
        : "r"(a[0]),"r"(a[1]),"r"(a[2]),"r"(a[3]), "r"(b[0]),"r"(b[1]),
          "f"(c[0]),"f"(c[1]),"f"(c[2]),"f"(c[3]));
}
__device__ __forceinline__ void ldsm4(uint32_t* r, uint32_t addr){
    asm volatile("ldmatrix.sync.aligned.m8n8.x4.shared.b16 {%0,%1,%2,%3}, [%4];"
        : "=r"(r[0]),"=r"(r[1]),"=r"(r[2]),"=r"(r[3]) : "r"(addr));
}
__device__ __forceinline__ void cpa(uint32_t dst, const void* src){
    asm volatile("cp.async.cg.shared.global [%0], [%1], 16;" :: "r"(dst), "l"(src));
}
__device__ __forceinline__ void cp_commit(){ asm volatile("cp.async.commit_group;" ::: "memory"); }
template<int N> __device__ __forceinline__ void cp_wait(){ asm volatile("cp.async.wait_group %0;" :: "n"(N) : "memory"); }

// ================= K1: 1x1 conv at mid slice =================
__global__ void conv_mid_kernel(const float* __restrict__ b,
                                const float* __restrict__ gw, const float* __restrict__ gb,
                                const float* __restrict__ tw, const float* __restrict__ tb,
                                const float* __restrict__ pw, const float* __restrict__ pb)
{
    __shared__ float ws[3*CI*CIN];
    __shared__ float bs[3*CI];
    int tid = threadIdx.x;
    for (int i = tid; i < CI*CIN; i += 256){
        ws[i] = gw[i]; ws[CI*CIN + i] = tw[i]; ws[2*CI*CIN + i] = pw[i];
    }
    if (tid < CI){ bs[tid] = gb[tid]; bs[CI+tid] = tb[tid]; bs[2*CI+tid] = pb[tid]; }
    __syncthreads();

    int pix = blockIdx.x*256 + tid;
    int batch = blockIdx.y;
    const float* bp = b + (size_t)batch*CIN*DD*NPIX + MIDOFF + pix;
    float acc[48];
    #pragma unroll
    for (int i = 0; i < 48; i++) acc[i] = bs[i];
    for (int c = 0; c < CIN; c++){
        float v = bp[(size_t)c*DD*NPIX];
        #pragma unroll
        for (int m = 0; m < 3; m++)
            #pragma unroll
            for (int ci = 0; ci < CI; ci++)
                acc[m*CI + ci] += ws[m*CI*CIN + ci*CIN + c] * v;
    }
    float* xo = g_X + (size_t)batch*3*CI*NPIX;
    #pragma unroll
    for (int i = 0; i < 48; i++) xo[(size_t)i*NPIX + pix] = acc[i];
}

// ================= K2a: init ones/zero rows of Vt =================
__global__ void vinit_kernel()
{
    int i = blockIdx.x*256 + threadIdx.x;     // 2*16*6400 = 204800
    int batch = i / (16*NLOC);
    int rem = i - batch*(16*NLOC);
    int r = rem / NLOC;
    int c = rem - r*NLOC;
    g_Vt[(size_t)batch*VROWS*NLOC + (size_t)(144 + r)*NLOC + c] =
        (r == 0) ? __float2half(1.f) : __float2half(0.f);
}

// ================= K2: unfold -> Qh(fp16 scaled), Kf(fp16), Vt(fp16 transposed) ===
__global__ void build_patches_kernel()
{
    int batch = blockIdx.z;
    int mat   = blockIdx.y;                    // 0=g->Q, 1=theta->V, 2=phi->K
    int idx   = blockIdx.x*256 + threadIdx.x;  // 921600
    int l, j;
    if (mat == 1){ j = idx / NLOC; l = idx - j*NLOC; }
    else         { l = idx / DH;   j = idx - l*DH;  }
    int ci = j/9, t = j%9, kr = t/3, kc = t%3;
    int ih = l/80, iw = l%80;
    int r = ih*2 + kr - 1, c = iw*2 + kc - 1;
    const float* X = g_X + ((size_t)(batch*3 + mat))*CI*NPIX;
    float v = 0.f;
    if ((unsigned)r < 160u && (unsigned)c < 160u) v = X[ci*NPIX + r*160 + c];

    if (mat == 0){
        g_Qh[(size_t)batch*NLOC*DH + idx] = __float2half_rn(v * 14.4269504088896340736f);
    } else if (mat == 1){
        g_Vt[(size_t)batch*VROWS*NLOC + idx] = __float2half_rn(v);
    } else {
        g_Kf[(size_t)batch*NLOC*DH + idx] = __float2half_rn(v);
    }
}

// ================= K3: flash attention, mma.sync (HMMA), 12 warps/key-split ======
#define BM   96
#define KSTR 152              // halves per K-tile row (304B, conflict-free ldsm)
#define VSTR 72               // halves per V-tile row (144B)
#define KTB  (64*KSTR*2)      // 19456 bytes
#define VTB  (VROWS*VSTR*2)   // 23040 bytes
#define BUFB (KTB+VTB)        // 42496
#define SMB_FLASH (3*BUFB)    // 127488
#define NTH  384

__device__ __forceinline__ void load_tiles(uint32_t smb, int buf,
                                           const __half* Kg, const __half* Vg,
                                           int kb, int tid)
{
    uint32_t kd = smb + buf*BUFB;
    const __half* ks = Kg + (size_t)kb*64*DH;
    #pragma unroll
    for (int j = 0; j < 3; j++){
        int id = tid + j*NTH;             // 64 rows x 18 chunks(16B) = 1152
        int r = id/18, c = id - r*18;
        cpa(kd + r*(KSTR*2) + c*16, ks + r*DH + c*8);
    }
    uint32_t vd = smb + buf*BUFB + KTB;
    const __half* vs = Vg + kb*64;
    #pragma unroll
    for (int j = 0; j < 4; j++){
        int id = tid + j*NTH;             // 160 rows x 8 chunks(16B) = 1280
        if (id < 1280){
            int r = id>>3, c = id&7;
            cpa(vd + r*(VSTR*2) + c*16, vs + (size_t)r*NLOC + c*8);
        }
    }
}

__global__ __launch_bounds__(NTH, 1) void flash_kernel()
{
    extern __shared__ char sm[];
    uint32_t smb = smem_u32(sm);
    const int tid = threadIdx.x, w = tid>>5, lane = tid&31;
    const int g = lane>>2, tig = lane&3;
    const int wp = w>>1;                 // row group 0..5
    const int hf = w&1;                  // key half 0/1
    const int qb = blockIdx.x, batch = blockIdx.y;

    const __half* Qg = g_Qh + (size_t)batch*NLOC*DH;
    const __half* Kg = g_Kf + (size_t)batch*NLOC*DH;
    const __half* Vg = g_Vt + (size_t)batch*VROWS*NLOC;
    __half*       Zg = g_Zh + (size_t)batch*NLOC*DH;

    // ---- Q fragments (fp16 direct), rows row0 and row0+8 ----
    const int row0 = qb*BM + wp*16 + g;
    const int r0c = min(row0, NLOC-1), r1c = min(row0+8, NLOC-1);
    uint32_t qh[36];
    #pragma unroll
    for (int t = 0; t < 9; t++){
        const __half* p0 = Qg + (size_t)r0c*DH + t*16 + tig*2;
        const __half* p1 = Qg + (size_t)r1c*DH + t*16 + tig*2;
        qh[4*t+0] = *(const uint32_t*)p0;
        qh[4*t+1] = *(const uint32_t*)p1;
        qh[4*t+2] = *(const uint32_t*)(p0 + 8);
        qh[4*t+3] = *(const uint32_t*)(p1 + 8);
    }

    // ldmatrix per-lane base offsets
    const int lm = lane>>3;
    const int lr = lane&7;
    const int lrow = lr + ((lm&2)<<2);
    const int lcol = (lm&1)*16;

    // oa[0..17]: O (144 dh). oa[18]: l column (col 144 live). Partial over key half.
    float oa[19][4];
    #pragma unroll
    for (int j = 0; j < 19; j++){ oa[j][0]=0.f; oa[j][1]=0.f; oa[j][2]=0.f; oa[j][3]=0.f; }
    float m0 = -1e30f, m1 = -1e30f;     // per-warp running max over OWN key half

    load_tiles(smb, 0, Kg, Vg, 0, tid); cp_commit();
    load_tiles(smb, 1, Kg, Vg, 1, tid); cp_commit();

    for (int t = 0; t < 100; t++){
        if (t + 2 < 100) cp_wait<1>(); else cp_wait<0>();
        __syncthreads();
        if (t+2 < 100){ load_tiles(smb, (t+2)%3, Kg, Vg, t+2, tid); cp_commit(); }

        const uint32_t kmb = smb + (t%3)*BUFB + (hf*32 + lrow)*(KSTR*2) + lcol;
        const uint32_t vmb = smb + (t%3)*BUFB + KTB + lrow*(VSTR*2) + lcol + hf*64;

        // ---- S = Q*K over this warp's 32 keys ----
        float sa[4][4];
        #pragma unroll
        for (int j = 0; j < 4; j++){ sa[j][0]=0.f; sa[j][1]=0.f; sa[j][2]=0.f; sa[j][3]=0.f; }
        #pragma unroll
        for (int kt = 0; kt < 9; kt++){
            uint32_t bb[2][4];
            ldsm4(bb[0], kmb + kt*32);
            ldsm4(bb[1], kmb + 16*(KSTR*2) + kt*32);
            mma16816(sa[0], &qh[4*kt], bb[0],   sa[0]);
            mma16816(sa[1], &qh[4*kt], bb[0]+2, sa[1]);
            mma16816(sa[2], &qh[4*kt], bb[1],   sa[2]);
            mma16816(sa[3], &qh[4*kt], bb[1]+2, sa[3]);
        }

        // ---- local max (per-warp, independent) ----
        float mx0 = fmaxf(fmaxf(sa[0][0], sa[0][1]), fmaxf(sa[1][0], sa[1][1]));
        float mx1 = fmaxf(fmaxf(sa[0][2], sa[0][3]), fmaxf(sa[1][2], sa[1][3]));
        mx0 = fmaxf(mx0, fmaxf(fmaxf(sa[2][0], sa[2][1]), fmaxf(sa[3][0], sa[3][1])));
        mx1 = fmaxf(mx1, fmaxf(fmaxf(sa[2][2], sa[2][3]), fmaxf(sa[3][2], sa[3][3])));

        if (!__all_sync(0xffffffffu, (mx0 <= m0) && (mx1 <= m1))){
            mx0 = fmaxf(mx0, __shfl_xor_sync(0xffffffffu, mx0, 1));
            mx0 = fmaxf(mx0, __shfl_xor_sync(0xffffffffu, mx0, 2));
            mx1 = fmaxf(mx1, __shfl_xor_sync(0xffffffffu, mx1, 1));
            mx1 = fmaxf(mx1, __shfl_xor_sync(0xffffffffu, mx1, 2));
            float m0n = fmaxf(m0, mx0), m1n = fmaxf(m1, mx1);
            float sc0 = ex2(m0 - m0n),  sc1 = ex2(m1 - m1n);
            m0 = m0n; m1 = m1n;
            #pragma unroll
            for (int j = 0; j < 19; j++){
                oa[j][0] *= sc0; oa[j][1] *= sc0;
                oa[j][2] *= sc1; oa[j][3] *= sc1;
            }
        }

        // ---- P fragments via fp16x2 exp2 ----
        uint32_t pa[2][4];
        #pragma unroll
        for (int k2 = 0; k2 < 2; k2++){
            pa[k2][0] = h2ex2(pkh(sa[2*k2][0]  - m0, sa[2*k2][1]  - m0));
            pa[k2][1] = h2ex2(pkh(sa[2*k2][2]  - m1, sa[2*k2][3]  - m1));
            pa[k2][2] = h2ex2(pkh(sa[2*k2+1][0]- m0, sa[2*k2+1][1]- m0));
            pa[k2][3] = h2ex2(pkh(sa[2*k2+1][2]- m1, sa[2*k2+1][3]- m1));
        }

        // ---- O += P * V over this warp's 32 keys (9 dh blocks + l block) ----
        #pragma unroll
        for (int k2 = 0; k2 < 2; k2++){
            #pragma unroll
            for (int np = 0; np < 9; np++){
                uint32_t bb[4];
                ldsm4(bb, vmb + np*16*(VSTR*2) + k2*32);
                mma16816(oa[2*np],   pa[k2], bb,   oa[2*np]);
                mma16816(oa[2*np+1], pa[k2], bb+2, oa[2*np+1]);
            }
            uint32_t bb[4];
            ldsm4(bb, vmb + 9*16*(VSTR*2) + k2*32);
            mma16816(oa[18], pa[k2], bb, oa[18]);
        }
    }

    // ================= merge warp pairs (odd -> smem, even combines) =============
    __syncthreads();                      // tile reads done; reuse smem
    float4* xO = (float4*)sm;             // [6 wp][32 lanes][20 f4]
    float*  xM = (float*)(sm + 61440);    // [6 wp][32 lanes][2]
    if (hf){
        float4* dst = xO + (size_t)wp*640 + lane*20;
        #pragma unroll
        for (int j = 0; j < 19; j++)
            dst[j] = make_float4(oa[j][0], oa[j][1], oa[j][2], oa[j][3]);
        float* mm = xM + wp*64 + lane*2;
        mm[0] = m0; mm[1] = m1;
    }
    __syncthreads();
    if (!hf){
        const float4* src = xO + (size_t)wp*640 + lane*20;
        const float* mm = xM + wp*64 + lane*2;
        float pm0 = mm[0], pm1 = mm[1];
        float ms0 = fmaxf(m0, pm0), ms1 = fmaxf(m1, pm1);
        float sA0 = ex2(m0 - ms0), sB0 = ex2(pm0 - ms0);
        float sA1 = ex2(m1 - ms1), sB1 = ex2(pm1 - ms1);
        #pragma unroll
        for (int j = 0; j < 19; j++){
            float4 p = src[j];
            oa[j][0] = oa[j][0]*sA0 + p.x*sB0;
            oa[j][1] = oa[j][1]*sA0 + p.y*sB0;
            oa[j][2] = oa[j][2]*sA1 + p.z*sB1;
            oa[j][3] = oa[j][3]*sA1 + p.w*sB1;
        }
        float l0 = __shfl_sync(0xffffffffu, oa[18][0], lane & 28);
        float l1 = __shfl_sync(0xffffffffu, oa[18][2], lane & 28);
        float i0 = 1.f/l0, i1 = 1.f/l1;
        if (row0 < NLOC){
            __half* z = Zg + (size_t)row0*DH + tig*2;
            #pragma unroll
            for (int j = 0; j < 18; j++)
                *(uint32_t*)(z + j*8) = pkh(oa[j][0]*i0, oa[j][1]*i0);
        }
        if (row0 + 8 < NLOC){
            __half* z = Zg + (size_t)(row0+8)*DH + tig*2;
            #pragma unroll
            for (int j = 0; j < 18; j++)
                *(uint32_t*)(z + j*8) = pkh(oa[j][2]*i1, oa[j][3]*i1);
        }
    }
}

// ================= K4: fused fold + W conv + residual add, float4 x 4 pixels =====
__global__ void fold_w_out_kernel(const float* __restrict__ Ww, const float* __restrict__ Wb,
                                  const float* __restrict__ bin, float* __restrict__ out)
{
    __shared__ float ws[32*CI];
    __shared__ float wb[32];
    int tid = threadIdx.x;
    int c0 = blockIdx.z*32;
    for (int i = tid; i < 32*CI; i += 256) ws[i] = Ww[c0*CI + i];
    if (tid < 32) wb[tid] = Wb[c0 + tid];
    __syncthreads();

    int pix0 = (blockIdx.x*256 + tid)*4;        // 25*256*4 = 25600
    int batch = blockIdx.y;
    int h = pix0 / 160;                         // same row for all 4 pixels
    int w0 = pix0 % 160;

    // row path (shared by the 4 pixels)
    int krs[2], ihs[2], nr = 0;
    if (!(h & 1)){ krs[0] = 1; ihs[0] = h >> 1; nr = 1; }
    else { if (h < 159){ krs[nr] = 0; ihs[nr] = (h+1) >> 1; nr++; } krs[nr] = 2; ihs[nr] = (h-1) >> 1; nr++; }

    const __half* Z = g_Zh + (size_t)batch*NLOC*DH;
    float acc[4][CI];
    #pragma unroll
    for (int p = 0; p < 4; p++)
        #pragma unroll
        for (int ci = 0; ci < CI; ci++) acc[p][ci] = 0.f;

    #pragma unroll
    for (int p = 0; p < 4; p++){
        int w = w0 + p;
        int kcs[2], iws[2], nc = 0;
        if (!(w & 1)){ kcs[0] = 1; iws[0] = w >> 1; nc = 1; }
        else { if (w < 159){ kcs[nc] = 0; iws[nc] = (w+1) >> 1; nc++; } kcs[nc] = 2; iws[nc] = (w-1) >> 1; nc++; }
        for (int a = 0; a < nr; a++)
            for (int bb = 0; bb < nc; bb++){
                int l = ihs[a]*80 + iws[bb];
                const __half* zp = Z + (size_t)l*DH + krs[a]*3 + kcs[bb];
                #pragma unroll
                for (int ci = 0; ci < CI; ci++) acc[p][ci] += __half2float(zp[ci*9]);
            }
        float inv = 1.f / (float)(nr*nc);
        #pragma unroll
        for (int ci = 0; ci < CI; ci++) acc[p][ci] *= inv;
    }

    const float* bp = bin + (size_t)batch*CIN*DD*NPIX + (size_t)c0*DD*NPIX + pix0;
    float*       op = out + (size_t)batch*CIN*DD*NPIX + (size_t)c0*DD*NPIX + pix0;
    #pragma unroll 2
    for (int c = 0; c < 32; c++){
        float y0 = wb[c], y1 = wb[c], y2 = wb[c], y3 = wb[c];
        #pragma unroll
        for (int ci = 0; ci < CI; ci++){
            float wv = ws[c*CI + ci];
            y0 += wv*acc[0][ci]; y1 += wv*acc[1][ci];
            y2 += wv*acc[2][ci]; y3 += wv*acc[3][ci];
        }
        const float* bc = bp + (size_t)c*DD*NPIX;
        float*       oc = op + (size_t)c*DD*NPIX;
        #pragma unroll
        for (int d = 0; d < DD; d++){
            float4 bv = *(const float4*)(bc + (size_t)d*NPIX);
            *(float4*)(oc + (size_t)d*NPIX) =
                make_float4(bv.x + y0, bv.y + y1, bv.z + y2, bv.w + y3);
        }
    }
}

// ================= launch =================
extern "C" void kernel_launch(void* const* d_in, const int* in_sizes, int n_in,
                              void* d_out, int out_size)
{
    const float* b  = (const float*)d_in[0];
    const float* gw = (const float*)d_in[1];
    const float* gb = (const float*)d_in[2];
    const float* tw = (const float*)d_in[3];
    const float* tb = (const float*)d_in[4];
    const float* pw = (const float*)d_in[5];
    const float* pb = (const float*)d_in[6];
    const float* Ww = (const float*)d_in[7];
    const float* Wb = (const float*)d_in[8];
    float* out = (float*)d_out;

    cudaFuncSetAttribute(flash_kernel, cudaFuncAttributeMaxDynamicSharedMemorySize, SMB_FLASH);

    conv_mid_kernel<<<dim3(100, 2), 256>>>(b, gw, gb, tw, tb, pw, pb);
    vinit_kernel<<<800, 256>>>();
    build_patches_kernel<<<dim3(3600, 3, 2), 256>>>();
    flash_kernel<<<dim3(67, 2), NTH, SMB_FLASH>>>();
    fold_w_out_kernel<<<dim3(25, 2, 2), 256>>>(Ww, Wb, b, out);
}

// round 15
// speedup vs baseline: 1.0934x; 1.0860x over previous
#include <cuda_runtime.h>
#include <cuda_fp16.h>
#include <cstdint>

#define NLOC 6400
#define DH   144
#define VROWS 160            // 144 dh + ones row (144) + 15 zero rows
#define NPIX 25600
#define CIN  64
#define CI   16
#define DD   8
#define MIDOFF (4*NPIX)

// ---------------- gmem scratch ----------------
__device__ float  g_X[2*3*CI*NPIX];
__device__ __half g_Qh[2*NLOC*DH + 32*DH];   // fp16, pre-scaled by 10*log2(e); padded
__device__ __half g_Kf[2*NLOC*DH];           // fp16 [loc][dh]
__device__ __half g_Vt[2*VROWS*NLOC];        // fp16 transposed [dh][loc], rows 144..159 = ones/zeros
__device__ __half g_Zh[2*NLOC*DH];           // fp16 attention output [l][ci*9+t]
__device__ __half g_Zt[2*NLOC*DH];           // fp16 permuted        [l][t*16+ci]

// ---------------- helpers ----------------
__device__ __forceinline__ uint32_t smem_u32(const void* p){
    uint32_t a; asm("{ .reg .u64 t; cvta.to.shared.u64 t, %1; cvt.u32.u64 %0, t; }" : "=r"(a) : "l"(p));
    return a;
}
__device__ __forceinline__ float ex2(float x){
    float y; asm("ex2.approx.ftz.f32 %0, %1;" : "=f"(y) : "f"(x)); return y;
}
// pack two fp32 -> fp16x2, lo half = first arg
__device__ __forceinline__ uint32_t pkh(float lo, float hi){
    uint32_t u; asm("cvt.rn.f16x2.f32 %0, %1, %2;" : "=r"(u) : "f"(hi), "f"(lo)); return u;
}
__device__ __forceinline__ uint32_t h2ex2(uint32_t x){
    uint32_t y; asm("ex2.approx.f16x2 %0, %1;" : "=r"(y) : "r"(x)); return y;
}
__device__ __forceinline__ void mma16816(float* d, const uint32_t* a, const uint32_t* b, const float* c){
    asm volatile("mma.sync.aligned.m16n8k16.row.col.f32.f16.f16.f32 "
        "{%0,%1,%2,%3}, {%4,%5,%6,%7}, {%8,%9}, {%10,%11,%12,%13};"
        : "=f"(d[0]),"=f"(d[1]),"=f"(d[2]),"=f"(d[3])
        : "r"(a[0]),"r"(a[1]),"r"(a[2]),"r"(a[3]), "r"(b[0]),"r"(b[1]),
          "f"(c[0]),"f"(c[1]),"f"(c[2]),"f"(c[3]));
}
__device__ __forceinline__ void ldsm4(uint32_t* r, uint32_t addr){
    asm volatile("ldmatrix.sync.aligned.m8n8.x4.shared.b16 {%0,%1,%2,%3}, [%4];"
        : "=r"(r[0]),"=r"(r[1]),"=r"(r[2]),"=r"(r[3]) : "r"(addr));
}
__device__ __forceinline__ void cpa(uint32_t dst, const void* src){
    asm volatile("cp.async.cg.shared.global [%0], [%1], 16;" :: "r"(dst), "l"(src));
}
__device__ __forceinline__ void cp_commit(){ asm volatile("cp.async.commit_group;" ::: "memory"); }
template<int N> __device__ __forceinline__ void cp_wait(){ asm volatile("cp.async.wait_group %0;" :: "n"(N) : "memory"); }

// ================= K1: 1x1 conv at mid slice =================
__global__ void conv_mid_kernel(const float* __restrict__ b,
                                const float* __restrict__ gw, const float* __restrict__ gb,
                                const float* __restrict__ tw, const float* __restrict__ tb,
                                const float* __restrict__ pw, const float* __restrict__ pb)
{
    __shared__ float ws[3*CI*CIN];
    __shared__ float bs[3*CI];
    int tid = threadIdx.x;
    for (int i = tid; i < CI*CIN; i += 256){
        ws[i] = gw[i]; ws[CI*CIN + i] = tw[i]; ws[2*CI*CIN + i] = pw[i];
    }
    if (tid < CI){ bs[tid] = gb[tid]; bs[CI+tid] = tb[tid]; bs[2*CI+tid] = pb[tid]; }
    __syncthreads();

    int pix = blockIdx.x*256 + tid;
    int batch = blockIdx.y;
    const float* bp = b + (size_t)batch*CIN*DD*NPIX + MIDOFF + pix;
    float acc[48];
    #pragma unroll
    for (int i = 0; i < 48; i++) acc[i] = bs[i];
    for (int c = 0; c < CIN; c++){
        float v = bp[(size_t)c*DD*NPIX];
        #pragma unroll
        for (int m = 0; m < 3; m++)
            #pragma unroll
            for (int ci = 0; ci < CI; ci++)
                acc[m*CI + ci] += ws[m*CI*CIN + ci*CIN + c] * v;
    }
    float* xo = g_X + (size_t)batch*3*CI*NPIX;
    #pragma unroll
    for (int i = 0; i < 48; i++) xo[(size_t)i*NPIX + pix] = acc[i];
}

// ================= K2a: init ones/zero rows of Vt =================
__global__ void vinit_kernel()
{
    int i = blockIdx.x*256 + threadIdx.x;     // 2*16*6400 = 204800
    int batch = i / (16*NLOC);
    int rem = i - batch*(16*NLOC);
    int r = rem / NLOC;
    int c = rem - r*NLOC;
    g_Vt[(size_t)batch*VROWS*NLOC + (size_t)(144 + r)*NLOC + c] =
        (r == 0) ? __float2half(1.f) : __float2half(0.f);
}

// ================= K2: unfold -> Qh(fp16 scaled), Kf(fp16), Vt(fp16 transposed) ===
__global__ void build_patches_kernel()
{
    int batch = blockIdx.z;
    int mat   = blockIdx.y;                    // 0=g->Q, 1=theta->V, 2=phi->K
    int idx   = blockIdx.x*256 + threadIdx.x;  // 921600
    int l, j;
    if (mat == 1){ j = idx / NLOC; l = idx - j*NLOC; }
    else         { l = idx / DH;   j = idx - l*DH;  }
    int ci = j/9, t = j%9, kr = t/3, kc = t%3;
    int ih = l/80, iw = l%80;
    int r = ih*2 + kr - 1, c = iw*2 + kc - 1;
    const float* X = g_X + ((size_t)(batch*3 + mat))*CI*NPIX;
    float v = 0.f;
    if ((unsigned)r < 160u && (unsigned)c < 160u) v = X[ci*NPIX + r*160 + c];

    if (mat == 0){
        g_Qh[(size_t)batch*NLOC*DH + idx] = __float2half_rn(v * 14.4269504088896340736f);
    } else if (mat == 1){
        g_Vt[(size_t)batch*VROWS*NLOC + idx] = __float2half_rn(v);
    } else {
        g_Kf[(size_t)batch*NLOC*DH + idx] = __float2half_rn(v);
    }
}

// ================= K3: flash attention, mma.sync (HMMA), 12 warps/key-split ======
#define BM   96
#define KSTR 152              // halves per K-tile row (304B, conflict-free ldsm)
#define VSTR 72               // halves per V-tile row (144B)
#define KTB  (64*KSTR*2)      // 19456 bytes
#define VTB  (VROWS*VSTR*2)   // 23040 bytes
#define BUFB (KTB+VTB)        // 42496
#define SMB_FLASH (3*BUFB)    // 127488
#define NTH  384

__device__ __forceinline__ void load_tiles(uint32_t smb, int buf,
                                           const __half* Kg, const __half* Vg,
                                           int kb, int tid)
{
    uint32_t kd = smb + buf*BUFB;
    const __half* ks = Kg + (size_t)kb*64*DH;
    #pragma unroll
    for (int j = 0; j < 3; j++){
        int id = tid + j*NTH;             // 64 rows x 18 chunks(16B) = 1152
        int r = id/18, c = id - r*18;
        cpa(kd + r*(KSTR*2) + c*16, ks + r*DH + c*8);
    }
    uint32_t vd = smb + buf*BUFB + KTB;
    const __half* vs = Vg + kb*64;
    #pragma unroll
    for (int j = 0; j < 4; j++){
        int id = tid + j*NTH;             // 160 rows x 8 chunks(16B) = 1280
        if (id < 1280){
            int r = id>>3, c = id&7;
            cpa(vd + r*(VSTR*2) + c*16, vs + (size_t)r*NLOC + c*8);
        }
    }
}

__global__ __launch_bounds__(NTH, 1) void flash_kernel()
{
    extern __shared__ char sm[];
    uint32_t smb = smem_u32(sm);
    const int tid = threadIdx.x, w = tid>>5, lane = tid&31;
    const int g = lane>>2, tig = lane&3;
    const int wp = w>>1;                 // row group 0..5
    const int hf = w&1;                  // key half 0/1
    const int qb = blockIdx.x, batch = blockIdx.y;

    const __half* Qg = g_Qh + (size_t)batch*NLOC*DH;
    const __half* Kg = g_Kf + (size_t)batch*NLOC*DH;
    const __half* Vg = g_Vt + (size_t)batch*VROWS*NLOC;
    __half*       Zg = g_Zh + (size_t)batch*NLOC*DH;

    // ---- Q fragments (fp16 direct), rows row0 and row0+8 ----
    const int row0 = qb*BM + wp*16 + g;
    const int r0c = min(row0, NLOC-1), r1c = min(row0+8, NLOC-1);
    uint32_t qh[36];
    #pragma unroll
    for (int t = 0; t < 9; t++){
        const __half* p0 = Qg + (size_t)r0c*DH + t*16 + tig*2;
        const __half* p1 = Qg + (size_t)r1c*DH + t*16 + tig*2;
        qh[4*t+0] = *(const uint32_t*)p0;
        qh[4*t+1] = *(const uint32_t*)p1;
        qh[4*t+2] = *(const uint32_t*)(p0 + 8);
        qh[4*t+3] = *(const uint32_t*)(p1 + 8);
    }

    // ldmatrix per-lane base offsets
    const int lm = lane>>3;
    const int lr = lane&7;
    const int lrow = lr + ((lm&2)<<2);
    const int lcol = (lm&1)*16;

    // oa[0..17]: O (144 dh). oa[18]: l column (col 144 live). Partial over key half.
    float oa[19][4];
    #pragma unroll
    for (int j = 0; j < 19; j++){ oa[j][0]=0.f; oa[j][1]=0.f; oa[j][2]=0.f; oa[j][3]=0.f; }
    float m0 = -1e30f, m1 = -1e30f;     // per-warp running max over OWN key half

    load_tiles(smb, 0, Kg, Vg, 0, tid); cp_commit();
    load_tiles(smb, 1, Kg, Vg, 1, tid); cp_commit();

    for (int t = 0; t < 100; t++){
        if (t + 2 < 100) cp_wait<1>(); else cp_wait<0>();
        __syncthreads();
        if (t+2 < 100){ load_tiles(smb, (t+2)%3, Kg, Vg, t+2, tid); cp_commit(); }

        const uint32_t kmb = smb + (t%3)*BUFB + (hf*32 + lrow)*(KSTR*2) + lcol;
        const uint32_t vmb = smb + (t%3)*BUFB + KTB + lrow*(VSTR*2) + lcol + hf*64;

        // ---- S = Q*K over this warp's 32 keys ----
        float sa[4][4];
        #pragma unroll
        for (int j = 0; j < 4; j++){ sa[j][0]=0.f; sa[j][1]=0.f; sa[j][2]=0.f; sa[j][3]=0.f; }
        #pragma unroll
        for (int kt = 0; kt < 9; kt++){
            uint32_t bb[2][4];
            ldsm4(bb[0], kmb + kt*32);
            ldsm4(bb[1], kmb + 16*(KSTR*2) + kt*32);
            mma16816(sa[0], &qh[4*kt], bb[0],   sa[0]);
            mma16816(sa[1], &qh[4*kt], bb[0]+2, sa[1]);
            mma16816(sa[2], &qh[4*kt], bb[1],   sa[2]);
            mma16816(sa[3], &qh[4*kt], bb[1]+2, sa[3]);
        }

        // ---- local max (per-warp, independent) ----
        float mx0 = fmaxf(fmaxf(sa[0][0], sa[0][1]), fmaxf(sa[1][0], sa[1][1]));
        float mx1 = fmaxf(fmaxf(sa[0][2], sa[0][3]), fmaxf(sa[1][2], sa[1][3]));
        mx0 = fmaxf(mx0, fmaxf(fmaxf(sa[2][0], sa[2][1]), fmaxf(sa[3][0], sa[3][1])));
        mx1 = fmaxf(mx1, fmaxf(fmaxf(sa[2][2], sa[2][3]), fmaxf(sa[3][2], sa[3][3])));

        if (!__all_sync(0xffffffffu, (mx0 <= m0) && (mx1 <= m1))){
            mx0 = fmaxf(mx0, __shfl_xor_sync(0xffffffffu, mx0, 1));
            mx0 = fmaxf(mx0, __shfl_xor_sync(0xffffffffu, mx0, 2));
            mx1 = fmaxf(mx1, __shfl_xor_sync(0xffffffffu, mx1, 1));
            mx1 = fmaxf(mx1, __shfl_xor_sync(0xffffffffu, mx1, 2));
            float m0n = fmaxf(m0, mx0), m1n = fmaxf(m1, mx1);
            float sc0 = ex2(m0 - m0n),  sc1 = ex2(m1 - m1n);
            m0 = m0n; m1 = m1n;
            #pragma unroll
            for (int j = 0; j < 19; j++){
                oa[j][0] *= sc0; oa[j][1] *= sc0;
                oa[j][2] *= sc1; oa[j][3] *= sc1;
            }
        }

        // ---- P fragments via fp16x2 exp2 ----
        uint32_t pa[2][4];
        #pragma unroll
        for (int k2 = 0; k2 < 2; k2++){
            pa[k2][0] = h2ex2(pkh(sa[2*k2][0]  - m0, sa[2*k2][1]  - m0));
            pa[k2][1] = h2ex2(pkh(sa[2*k2][2]  - m1, sa[2*k2][3]  - m1));
            pa[k2][2] = h2ex2(pkh(sa[2*k2+1][0]- m0, sa[2*k2+1][1]- m0));
            pa[k2][3] = h2ex2(pkh(sa[2*k2+1][2]- m1, sa[2*k2+1][3]- m1));
        }

        // ---- O += P * V over this warp's 32 keys (9 dh blocks + l block) ----
        #pragma unroll
        for (int k2 = 0; k2 < 2; k2++){
            #pragma unroll
            for (int np = 0; np < 9; np++){
                uint32_t bb[4];
                ldsm4(bb, vmb + np*16*(VSTR*2) + k2*32);
                mma16816(oa[2*np],   pa[k2], bb,   oa[2*np]);
                mma16816(oa[2*np+1], pa[k2], bb+2, oa[2*np+1]);
            }
            uint32_t bb[4];
            ldsm4(bb, vmb + 9*16*(VSTR*2) + k2*32);
            mma16816(oa[18], pa[k2], bb, oa[18]);
        }
    }

    // ================= merge warp pairs (odd -> smem, even combines) =============
    __syncthreads();                      // tile reads done; reuse smem
    float4* xO = (float4*)sm;             // [6 wp][32 lanes][20 f4]
    float*  xM = (float*)(sm + 61440);    // [6 wp][32 lanes][2]
    if (hf){
        float4* dst = xO + (size_t)wp*640 + lane*20;
        #pragma unroll
        for (int j = 0; j < 19; j++)
            dst[j] = make_float4(oa[j][0], oa[j][1], oa[j][2], oa[j][3]);
        float* mm = xM + wp*64 + lane*2;
        mm[0] = m0; mm[1] = m1;
    }
    __syncthreads();
    if (!hf){
        const float4* src = xO + (size_t)wp*640 + lane*20;
        const float* mm = xM + wp*64 + lane*2;
        float pm0 = mm[0], pm1 = mm[1];
        float ms0 = fmaxf(m0, pm0), ms1 = fmaxf(m1, pm1);
        float sA0 = ex2(m0 - ms0), sB0 = ex2(pm0 - ms0);
        float sA1 = ex2(m1 - ms1), sB1 = ex2(pm1 - ms1);
        #pragma unroll
        for (int j = 0; j < 19; j++){
            float4 p = src[j];
            oa[j][0] = oa[j][0]*sA0 + p.x*sB0;
            oa[j][1] = oa[j][1]*sA0 + p.y*sB0;
            oa[j][2] = oa[j][2]*sA1 + p.z*sB1;
            oa[j][3] = oa[j][3]*sA1 + p.w*sB1;
        }
        float l0 = __shfl_sync(0xffffffffu, oa[18][0], lane & 28);
        float l1 = __shfl_sync(0xffffffffu, oa[18][2], lane & 28);
        float i0 = 1.f/l0, i1 = 1.f/l1;
        if (row0 < NLOC){
            __half* z = Zg + (size_t)row0*DH + tig*2;
            #pragma unroll
            for (int j = 0; j < 18; j++)
                *(uint32_t*)(z + j*8) = pkh(oa[j][0]*i0, oa[j][1]*i0);
        }
        if (row0 + 8 < NLOC){
            __half* z = Zg + (size_t)(row0+8)*DH + tig*2;
            #pragma unroll
            for (int j = 0; j < 18; j++)
                *(uint32_t*)(z + j*8) = pkh(oa[j][2]*i1, oa[j][3]*i1);
        }
    }
}

// ================= K3b: Z permute  [l][ci*9+t] -> [l][t*16+ci] =================
__global__ void ztrans_kernel()
{
    __shared__ __half zs[32*DH];
    int tid = threadIdx.x;
    int l0 = blockIdx.x*32;               // 200 blocks
    int batch = blockIdx.y;
    const uint32_t* src = (const uint32_t*)(g_Zh + (size_t)batch*NLOC*DH + (size_t)l0*DH);
    uint32_t* zs32 = (uint32_t*)zs;
    #pragma unroll
    for (int j = 0; j < 9; j++) zs32[tid + j*256] = src[tid + j*256];
    __syncthreads();
    __half* dst = g_Zt + (size_t)batch*NLOC*DH + (size_t)l0*DH;
    #pragma unroll
    for (int j = 0; j < 18; j++){
        int idx = tid + j*256;            // 4608
        int loc = idx / DH, jo = idx - loc*DH;
        int t = jo >> 4, ci = jo & 15;    // DH = 9*16
        dst[idx] = zs[loc*DH + ci*9 + t];
    }
}

// ================= K4: fused fold + W conv + residual add (c-half split) =========
__global__ void fold_w_out_kernel(const float* __restrict__ Ww, const float* __restrict__ Wb,
                                  const float* __restrict__ bin, float* __restrict__ out)
{
    __shared__ float ws[32*CI];
    __shared__ float wb[32];
    int tid = threadIdx.x;
    int c0 = blockIdx.z*32;
    for (int i = tid; i < 32*CI; i += 256) ws[i] = Ww[c0*CI + i];
    if (tid < 32) wb[tid] = Wb[c0 + tid];
    __syncthreads();

    int pix = blockIdx.x*256 + tid;
    int batch = blockIdx.y;
    int h = pix / 160, w = pix % 160;

    int krs[2], ihs[2], nr = 0;
    if (!(h & 1)){ krs[0] = 1; ihs[0] = h >> 1; nr = 1; }
    else { if (h < 159){ krs[nr] = 0; ihs[nr] = (h+1) >> 1; nr++; } krs[nr] = 2; ihs[nr] = (h-1) >> 1; nr++; }
    int kcs[2], iws[2], nc = 0;
    if (!(w & 1)){ kcs[0] = 1; iws[0] = w >> 1; nc = 1; }
    else { if (w < 159){ kcs[nc] = 0; iws[nc] = (w+1) >> 1; nc++; } kcs[nc] = 2; iws[nc] = (w-1) >> 1; nc++; }

    const __half* Z = g_Zt + (size_t)batch*NLOC*DH;
    float acc[CI];
    #pragma unroll
    for (int ci = 0; ci < CI; ci++) acc[ci] = 0.f;
    for (int a = 0; a < nr; a++)
        for (int bb = 0; bb < nc; bb++){
            int l = ihs[a]*80 + iws[bb];
            // 16 contiguous halves = 32B: two uint4 vector loads
            const uint4* zp = (const uint4*)(Z + (size_t)l*DH + (krs[a]*3 + kcs[bb])*16);
            uint4 v0 = zp[0], v1 = zp[1];
            const __half2* h0 = (const __half2*)&v0;
            const __half2* h1 = (const __half2*)&v1;
            #pragma unroll
            for (int p = 0; p < 4; p++){
                float2 f0 = __half22float2(h0[p]);
                float2 f1 = __half22float2(h1[p]);
                acc[2*p+0] += f0.x; acc[2*p+1] += f0.y;
                acc[8+2*p+0] += f1.x; acc[8+2*p+1] += f1.y;
            }
        }
    float inv = 1.f / (float)(nr*nc);
    #pragma unroll
    for (int ci = 0; ci < CI; ci++) acc[ci] *= inv;

    const float* bp = bin + (size_t)batch*CIN*DD*NPIX + (size_t)c0*DD*NPIX + pix;
    float*       op = out + (size_t)batch*CIN*DD*NPIX + (size_t)c0*DD*NPIX + pix;
    #pragma unroll 2
    for (int c = 0; c < 32; c++){
        float y = wb[c];
        #pragma unroll
        for (int ci = 0; ci < CI; ci++) y += ws[c*CI + ci]*acc[ci];
        const float* bc = bp + (size_t)c*DD*NPIX;
        float*       oc = op + (size_t)c*DD*NPIX;
        #pragma unroll
        for (int d = 0; d < DD; d++)
            oc[(size_t)d*NPIX] = bc[(size_t)d*NPIX] + y;
    }
}

// ================= launch =================
extern "C" void kernel_launch(void* const* d_in, const int* in_sizes, int n_in,
                              void* d_out, int out_size)
{
    const float* b  = (const float*)d_in[0];
    const float* gw = (const float*)d_in[1];
    const float* gb = (const float*)d_in[2];
    const float* tw = (const float*)d_in[3];
    const float* tb = (const float*)d_in[4];
    const float* pw = (const float*)d_in[5];
    const float* pb = (const float*)d_in[6];
    const float* Ww = (const float*)d_in[7];
    const float* Wb = (const float*)d_in[8];
    float* out = (float*)d_out;

    cudaFuncSetAttribute(flash_kernel, cudaFuncAttributeMaxDynamicSharedMemorySize, SMB_FLASH);

    conv_mid_kernel<<<dim3(100, 2), 256>>>(b, gw, gb, tw, tb, pw, pb);
    vinit_kernel<<<800, 256>>>();
    build_patches_kernel<<<dim3(3600, 3, 2), 256>>>();
    flash_kernel<<<dim3(67, 2), NTH, SMB_FLASH>>>();
    ztrans_kernel<<<dim3(200, 2), 256>>>();
    fold_w_out_kernel<<<dim3(100, 2, 2), 256>>>(Ww, Wb, b, out);
}

// round 16
// speedup vs baseline: 1.1143x; 1.0192x over previous
#include <cuda_runtime.h>
#include <cuda_fp16.h>
#include <cstdint>

#define NLOC 6400
#define DH   144
#define VROWS 160            // 144 dh + ones row (144) + 15 zero rows
#define NPIX 25600
#define CIN  64
#define CI   16
#define DD   8
#define MIDOFF (4*NPIX)

// ---------------- gmem scratch ----------------
__device__ float  g_X[2*3*CI*NPIX];
__device__ __half g_Qh[2*NLOC*DH + 32*DH];   // fp16, pre-scaled by 10*log2(e); padded
__device__ __half g_Kf[2*NLOC*DH];           // fp16 [loc][dh]
__device__ __half g_Vt[2*VROWS*NLOC];        // fp16 transposed [dh][loc], rows 144..159 = ones/zeros
__device__ __half g_Zt[2*NLOC*DH];           // fp16 attention output, permuted [l][t*16+ci]

// ---------------- helpers ----------------
__device__ __forceinline__ uint32_t smem_u32(const void* p){
    uint32_t a; asm("{ .reg .u64 t; cvta.to.shared.u64 t, %1; cvt.u32.u64 %0, t; }" : "=r"(a) : "l"(p));
    return a;
}
__device__ __forceinline__ float ex2(float x){
    float y; asm("ex2.approx.ftz.f32 %0, %1;" : "=f"(y) : "f"(x)); return y;
}
// pack two fp32 -> fp16x2, lo half = first arg
__device__ __forceinline__ uint32_t pkh(float lo, float hi){
    uint32_t u; asm("cvt.rn.f16x2.f32 %0, %1, %2;" : "=r"(u) : "f"(hi), "f"(lo)); return u;
}
__device__ __forceinline__ uint32_t h2ex2(uint32_t x){
    uint32_t y; asm("ex2.approx.f16x2 %0, %1;" : "=r"(y) : "r"(x)); return y;
}
__device__ __forceinline__ void mma16816(float* d, const uint32_t* a, const uint32_t* b, const float* c){
    asm volatile("mma.sync.aligned.m16n8k16.row.col.f32.f16.f16.f32 "
        "{%0,%1,%2,%3}, {%4,%5,%6,%7}, {%8,%9}, {%10,%11,%12,%13};"
        : "=f"(d[0]),"=f"(d[1]),"=f"(d[2]),"=f"(d[3])
        : "r"(a[0]),"r"(a[1]),"r"(a[2]),"r"(a[3]), "r"(b[0]),"r"(b[1]),
          "f"(c[0]),"f"(c[1]),"f"(c[2]),"f"(c[3]));
}
__device__ __forceinline__ void ldsm4(uint32_t* r, uint32_t addr){
    asm volatile("ldmatrix.sync.aligned.m8n8.x4.shared.b16 {%0,%1,%2,%3}, [%4];"
        : "=r"(r[0]),"=r"(r[1]),"=r"(r[2]),"=r"(r[3]) : "r"(addr));
}
__device__ __forceinline__ void cpa(uint32_t dst, const void* src){
    asm volatile("cp.async.cg.shared.global [%0], [%1], 16;" :: "r"(dst), "l"(src));
}
__device__ __forceinline__ void cp_commit(){ asm volatile("cp.async.commit_group;" ::: "memory"); }
template<int N> __device__ __forceinline__ void cp_wait(){ asm volatile("cp.async.wait_group %0;" :: "n"(N) : "memory"); }

// ================= K1: 1x1 conv at mid slice =================
__global__ void conv_mid_kernel(const float* __restrict__ b,
                                const float* __restrict__ gw, const float* __restrict__ gb,
                                const float* __restrict__ tw, const float* __restrict__ tb,
                                const float* __restrict__ pw, const float* __restrict__ pb)
{
    __shared__ float ws[3*CI*CIN];
    __shared__ float bs[3*CI];
    int tid = threadIdx.x;
    for (int i = tid; i < CI*CIN; i += 256){
        ws[i] = gw[i]; ws[CI*CIN + i] = tw[i]; ws[2*CI*CIN + i] = pw[i];
    }
    if (tid < CI){ bs[tid] = gb[tid]; bs[CI+tid] = tb[tid]; bs[2*CI+tid] = pb[tid]; }
    __syncthreads();

    int pix = blockIdx.x*256 + tid;
    int batch = blockIdx.y;
    const float* bp = b + (size_t)batch*CIN*DD*NPIX + MIDOFF + pix;
    float acc[48];
    #pragma unroll
    for (int i = 0; i < 48; i++) acc[i] = bs[i];
    for (int c = 0; c < CIN; c++){
        float v = bp[(size_t)c*DD*NPIX];
        #pragma unroll
        for (int m = 0; m < 3; m++)
            #pragma unroll
            for (int ci = 0; ci < CI; ci++)
                acc[m*CI + ci] += ws[m*CI*CIN + ci*CIN + c] * v;
    }
    float* xo = g_X + (size_t)batch*3*CI*NPIX;
    #pragma unroll
    for (int i = 0; i < 48; i++) xo[(size_t)i*NPIX + pix] = acc[i];
}

// ================= K2a: init ones/zero rows of Vt =================
__global__ void vinit_kernel()
{
    int i = blockIdx.x*256 + threadIdx.x;     // 2*16*6400 = 204800
    int batch = i / (16*NLOC);
    int rem = i - batch*(16*NLOC);
    int r = rem / NLOC;
    int c = rem - r*NLOC;
    g_Vt[(size_t)batch*VROWS*NLOC + (size_t)(144 + r)*NLOC + c] =
        (r == 0) ? __float2half(1.f) : __float2half(0.f);
}

// ================= K2: unfold -> Qh(fp16 scaled), Kf(fp16), Vt(fp16 transposed) ===
__global__ void build_patches_kernel()
{
    int batch = blockIdx.z;
    int mat   = blockIdx.y;                    // 0=g->Q, 1=theta->V, 2=phi->K
    int idx   = blockIdx.x*256 + threadIdx.x;  // 921600
    int l, j;
    if (mat == 1){ j = idx / NLOC; l = idx - j*NLOC; }
    else         { l = idx / DH;   j = idx - l*DH;  }
    int ci = j/9, t = j%9, kr = t/3, kc = t%3;
    int ih = l/80, iw = l%80;
    int r = ih*2 + kr - 1, c = iw*2 + kc - 1;
    const float* X = g_X + ((size_t)(batch*3 + mat))*CI*NPIX;
    float v = 0.f;
    if ((unsigned)r < 160u && (unsigned)c < 160u) v = X[ci*NPIX + r*160 + c];

    if (mat == 0){
        g_Qh[(size_t)batch*NLOC*DH + idx] = __float2half_rn(v * 14.4269504088896340736f);
    } else if (mat == 1){
        g_Vt[(size_t)batch*VROWS*NLOC + idx] = __float2half_rn(v);
    } else {
        g_Kf[(size_t)batch*NLOC*DH + idx] = __float2half_rn(v);
    }
}

// ================= K3: flash attention, mma.sync (HMMA), 12 warps/key-split ======
#define BM   96
#define KSTR 152              // halves per K-tile row (304B, conflict-free ldsm)
#define VSTR 72               // halves per V-tile row (144B)
#define KTB  (64*KSTR*2)      // 19456 bytes
#define VTB  (VROWS*VSTR*2)   // 23040 bytes
#define BUFB (KTB+VTB)        // 42496
#define SMB_FLASH (4*BUFB)    // 169984
#define NTH  384

__device__ __forceinline__ void load_tiles(uint32_t smb, int buf,
                                           const __half* Kg, const __half* Vg,
                                           int kb, int tid)
{
    uint32_t kd = smb + buf*BUFB;
    const __half* ks = Kg + (size_t)kb*64*DH;
    #pragma unroll
    for (int j = 0; j < 3; j++){
        int id = tid + j*NTH;             // 64 rows x 18 chunks(16B) = 1152
        int r = id/18, c = id - r*18;
        cpa(kd + r*(KSTR*2) + c*16, ks + r*DH + c*8);
    }
    uint32_t vd = smb + buf*BUFB + KTB;
    const __half* vs = Vg + kb*64;
    #pragma unroll
    for (int j = 0; j < 4; j++){
        int id = tid + j*NTH;             // 160 rows x 8 chunks(16B) = 1280
        if (id < 1280){
            int r = id>>3, c = id&7;
            cpa(vd + r*(VSTR*2) + c*16, vs + (size_t)r*NLOC + c*8);
        }
    }
}

__global__ __launch_bounds__(NTH, 1) void flash_kernel()
{
    extern __shared__ char sm[];
    uint32_t smb = smem_u32(sm);
    const int tid = threadIdx.x, w = tid>>5, lane = tid&31;
    const int g = lane>>2, tig = lane&3;
    const int wp = w>>1;                 // row group 0..5
    const int hf = w&1;                  // key half 0/1
    const int qb = blockIdx.x, batch = blockIdx.y;

    const __half* Qg = g_Qh + (size_t)batch*NLOC*DH;
    const __half* Kg = g_Kf + (size_t)batch*NLOC*DH;
    const __half* Vg = g_Vt + (size_t)batch*VROWS*NLOC;

    // ---- Q fragments (fp16 direct), rows row0 and row0+8 ----
    const int row0 = qb*BM + wp*16 + g;
    const int r0c = min(row0, NLOC-1), r1c = min(row0+8, NLOC-1);
    uint32_t qh[36];
    #pragma unroll
    for (int t = 0; t < 9; t++){
        const __half* p0 = Qg + (size_t)r0c*DH + t*16 + tig*2;
        const __half* p1 = Qg + (size_t)r1c*DH + t*16 + tig*2;
        qh[4*t+0] = *(const uint32_t*)p0;
        qh[4*t+1] = *(const uint32_t*)p1;
        qh[4*t+2] = *(const uint32_t*)(p0 + 8);
        qh[4*t+3] = *(const uint32_t*)(p1 + 8);
    }

    // ldmatrix per-lane base offsets
    const int lm = lane>>3;
    const int lr = lane&7;
    const int lrow = lr + ((lm&2)<<2);
    const int lcol = (lm&1)*16;

    // oa[0..17]: O (144 dh). oa[18]: l column (col 144 live). Partial over key half.
    float oa[19][4];
    #pragma unroll
    for (int j = 0; j < 19; j++){ oa[j][0]=0.f; oa[j][1]=0.f; oa[j][2]=0.f; oa[j][3]=0.f; }
    float m0 = -1e30f, m1 = -1e30f;     // per-warp running max over OWN key half

    load_tiles(smb, 0, Kg, Vg, 0, tid); cp_commit();
    load_tiles(smb, 1, Kg, Vg, 1, tid); cp_commit();

    for (int tt = 0; tt < 50; tt++){
        __syncthreads();                 // all warps done with chunks 2tt-2, 2tt+3's buffers
        if (tt < 49){
            load_tiles(smb, (2*tt+2)&3, Kg, Vg, 2*tt+2, tid); cp_commit();
            load_tiles(smb, (2*tt+3)&3, Kg, Vg, 2*tt+3, tid); cp_commit();
            cp_wait<2>();                // chunks 2tt, 2tt+1 resident
        } else {
            cp_wait<0>();
        }

        #pragma unroll
        for (int u = 0; u < 2; u++){
            const int t = 2*tt + u;
            const uint32_t kmb = smb + (t&3)*BUFB + (hf*32 + lrow)*(KSTR*2) + lcol;
            const uint32_t vmb = smb + (t&3)*BUFB + KTB + lrow*(VSTR*2) + lcol + hf*64;

            // ---- S = Q*K over this warp's 32 keys ----
            float sa[4][4];
            #pragma unroll
            for (int j = 0; j < 4; j++){ sa[j][0]=0.f; sa[j][1]=0.f; sa[j][2]=0.f; sa[j][3]=0.f; }
            #pragma unroll
            for (int kt = 0; kt < 9; kt++){
                uint32_t bb[2][4];
                ldsm4(bb[0], kmb + kt*32);
                ldsm4(bb[1], kmb + 16*(KSTR*2) + kt*32);
                mma16816(sa[0], &qh[4*kt], bb[0],   sa[0]);
                mma16816(sa[1], &qh[4*kt], bb[0]+2, sa[1]);
                mma16816(sa[2], &qh[4*kt], bb[1],   sa[2]);
                mma16816(sa[3], &qh[4*kt], bb[1]+2, sa[3]);
            }

            // ---- local max (per-warp, independent) ----
            float mx0 = fmaxf(fmaxf(sa[0][0], sa[0][1]), fmaxf(sa[1][0], sa[1][1]));
            float mx1 = fmaxf(fmaxf(sa[0][2], sa[0][3]), fmaxf(sa[1][2], sa[1][3]));
            mx0 = fmaxf(mx0, fmaxf(fmaxf(sa[2][0], sa[2][1]), fmaxf(sa[3][0], sa[3][1])));
            mx1 = fmaxf(mx1, fmaxf(fmaxf(sa[2][2], sa[2][3]), fmaxf(sa[3][2], sa[3][3])));

            if (!__all_sync(0xffffffffu, (mx0 <= m0) && (mx1 <= m1))){
                mx0 = fmaxf(mx0, __shfl_xor_sync(0xffffffffu, mx0, 1));
                mx0 = fmaxf(mx0, __shfl_xor_sync(0xffffffffu, mx0, 2));
                mx1 = fmaxf(mx1, __shfl_xor_sync(0xffffffffu, mx1, 1));
                mx1 = fmaxf(mx1, __shfl_xor_sync(0xffffffffu, mx1, 2));
                float m0n = fmaxf(m0, mx0), m1n = fmaxf(m1, mx1);
                float sc0 = ex2(m0 - m0n),  sc1 = ex2(m1 - m1n);
                m0 = m0n; m1 = m1n;
                #pragma unroll
                for (int j = 0; j < 19; j++){
                    oa[j][0] *= sc0; oa[j][1] *= sc0;
                    oa[j][2] *= sc1; oa[j][3] *= sc1;
                }
            }

            // ---- P fragments via fp16x2 exp2 ----
            uint32_t pa[2][4];
            #pragma unroll
            for (int k2 = 0; k2 < 2; k2++){
                pa[k2][0] = h2ex2(pkh(sa[2*k2][0]  - m0, sa[2*k2][1]  - m0));
                pa[k2][1] = h2ex2(pkh(sa[2*k2][2]  - m1, sa[2*k2][3]  - m1));
                pa[k2][2] = h2ex2(pkh(sa[2*k2+1][0]- m0, sa[2*k2+1][1]- m0));
                pa[k2][3] = h2ex2(pkh(sa[2*k2+1][2]- m1, sa[2*k2+1][3]- m1));
            }

            // ---- O += P * V over this warp's 32 keys (9 dh blocks + l block) ----
            #pragma unroll
            for (int k2 = 0; k2 < 2; k2++){
                #pragma unroll
                for (int np = 0; np < 9; np++){
                    uint32_t bb[4];
                    ldsm4(bb, vmb + np*16*(VSTR*2) + k2*32);
                    mma16816(oa[2*np],   pa[k2], bb,   oa[2*np]);
                    mma16816(oa[2*np+1], pa[k2], bb+2, oa[2*np+1]);
                }
                uint32_t bb[4];
                ldsm4(bb, vmb + 9*16*(VSTR*2) + k2*32);
                mma16816(oa[18], pa[k2], bb, oa[18]);
            }
        }
    }

    // ================= merge warp pairs (odd -> smem, even combines) =============
    __syncthreads();                      // tile reads done; reuse smem
    float4* xO = (float4*)sm;             // [6 wp][32 lanes][20 f4]
    float*  xM = (float*)(sm + 61440);    // [6 wp][32 lanes][2]
    if (hf){
        float4* dst = xO + (size_t)wp*640 + lane*20;
        #pragma unroll
        for (int j = 0; j < 19; j++)
            dst[j] = make_float4(oa[j][0], oa[j][1], oa[j][2], oa[j][3]);
        float* mm = xM + wp*64 + lane*2;
        mm[0] = m0; mm[1] = m1;
    }
    __syncthreads();
    float i0 = 0.f, i1 = 0.f;
    if (!hf){
        const float4* src = xO + (size_t)wp*640 + lane*20;
        const float* mm = xM + wp*64 + lane*2;
        float pm0 = mm[0], pm1 = mm[1];
        float ms0 = fmaxf(m0, pm0), ms1 = fmaxf(m1, pm1);
        float sA0 = ex2(m0 - ms0), sB0 = ex2(pm0 - ms0);
        float sA1 = ex2(m1 - ms1), sB1 = ex2(pm1 - ms1);
        #pragma unroll
        for (int j = 0; j < 19; j++){
            float4 p = src[j];
            oa[j][0] = oa[j][0]*sA0 + p.x*sB0;
            oa[j][1] = oa[j][1]*sA0 + p.y*sB0;
            oa[j][2] = oa[j][2]*sA1 + p.z*sB1;
            oa[j][3] = oa[j][3]*sA1 + p.w*sB1;
        }
        float l0 = __shfl_sync(0xffffffffu, oa[18][0], lane & 28);
        float l1 = __shfl_sync(0xffffffffu, oa[18][2], lane & 28);
        i0 = 1.f/l0; i1 = 1.f/l1;
    }
    __syncthreads();                      // xO reads done; reuse smem for fp16 stage

    // ---- stage normalized O (fp16) in smem [96 rows][144 dh] ----
    __half* zs = (__half*)sm;
    if (!hf){
        int rl0 = wp*16 + g, rl1 = rl0 + 8;
        #pragma unroll
        for (int j = 0; j < 18; j++){
            *(uint32_t*)(zs + rl0*DH + tig*2 + j*8) = pkh(oa[j][0]*i0, oa[j][1]*i0);
            *(uint32_t*)(zs + rl1*DH + tig*2 + j*8) = pkh(oa[j][2]*i1, oa[j][3]*i1);
        }
    }
    __syncthreads();

    // ---- permuted coalesced write: Zt[l][t*16+ci] ----
    __half* Zt = g_Zt + (size_t)batch*NLOC*DH;
    #pragma unroll
    for (int k = 0; k < 18; k++){
        int i = tid + k*NTH;              // 6912 = 96 rows * 72 pairs
        int row = i/72, q = i - row*72;
        int t2 = q>>3, ci2 = (q&7)*2;
        int grow = qb*BM + row;
        if (grow < NLOC){
            __half2 hv = __halves2half2(zs[row*DH + ci2*9 + t2], zs[row*DH + (ci2+1)*9 + t2]);
            *(uint32_t*)(Zt + (size_t)grow*DH + t2*16 + ci2) = *(uint32_t*)&hv;
        }
    }
}

// ================= K4: fused fold + W conv + residual add (c-half split) =========
__global__ void fold_w_out_kernel(const float* __restrict__ Ww, const float* __restrict__ Wb,
                                  const float* __restrict__ bin, float* __restrict__ out)
{
    __shared__ float ws[32*CI];
    __shared__ float wb[32];
    int tid = threadIdx.x;
    int c0 = blockIdx.z*32;
    for (int i = tid; i < 32*CI; i += 256) ws[i] = Ww[c0*CI + i];
    if (tid < 32) wb[tid] = Wb[c0 + tid];
    __syncthreads();

    int pix = blockIdx.x*256 + tid;
    int batch = blockIdx.y;
    int h = pix / 160, w = pix % 160;

    int krs[2], ihs[2], nr = 0;
    if (!(h & 1)){ krs[0] = 1; ihs[0] = h >> 1; nr = 1; }
    else { if (h < 159){ krs[nr] = 0; ihs[nr] = (h+1) >> 1; nr++; } krs[nr] = 2; ihs[nr] = (h-1) >> 1; nr++; }
    int kcs[2], iws[2], nc = 0;
    if (!(w & 1)){ kcs[0] = 1; iws[0] = w >> 1; nc = 1; }
    else { if (w < 159){ kcs[nc] = 0; iws[nc] = (w+1) >> 1; nc++; } kcs[nc] = 2; iws[nc] = (w-1) >> 1; nc++; }

    const __half* Z = g_Zt + (size_t)batch*NLOC*DH;
    float acc[CI];
    #pragma unroll
    for (int ci = 0; ci < CI; ci++) acc[ci] = 0.f;
    for (int a = 0; a < nr; a++)
        for (int bb = 0; bb < nc; bb++){
            int l = ihs[a]*80 + iws[bb];
            const uint4* zp = (const uint4*)(Z + (size_t)l*DH + (krs[a]*3 + kcs[bb])*16);
            uint4 v0 = zp[0], v1 = zp[1];
            const __half2* h0 = (const __half2*)&v0;
            const __half2* h1 = (const __half2*)&v1;
            #pragma unroll
            for (int p = 0; p < 4; p++){
                float2 f0 = __half22float2(h0[p]);
                float2 f1 = __half22float2(h1[p]);
                acc[2*p+0] += f0.x; acc[2*p+1] += f0.y;
                acc[8+2*p+0] += f1.x; acc[8+2*p+1] += f1.y;
            }
        }
    float inv = 1.f / (float)(nr*nc);
    #pragma unroll
    for (int ci = 0; ci < CI; ci++) acc[ci] *= inv;

    const float* bp = bin + (size_t)batch*CIN*DD*NPIX + (size_t)c0*DD*NPIX + pix;
    float*       op = out + (size_t)batch*CIN*DD*NPIX + (size_t)c0*DD*NPIX + pix;
    #pragma unroll 2
    for (int c = 0; c < 32; c++){
        float y = wb[c];
        #pragma unroll
        for (int ci = 0; ci < CI; ci++) y += ws[c*CI + ci]*acc[ci];
        const float* bc = bp + (size_t)c*DD*NPIX;
        float*       oc = op + (size_t)c*DD*NPIX;
        #pragma unroll
        for (int d = 0; d < DD; d++)
            oc[(size_t)d*NPIX] = bc[(size_t)d*NPIX] + y;
    }
}

// ================= launch =================
extern "C" void kernel_launch(void* const* d_in, const int* in_sizes, int n_in,
                              void* d_out, int out_size)
{
    const float* b  = (const float*)d_in[0];
    const float* gw = (const float*)d_in[1];
    const float* gb = (const float*)d_in[2];
    const float* tw = (const float*)d_in[3];
    const float* tb = (const float*)d_in[4];
    const float* pw = (const float*)d_in[5];
    const float* pb = (const float*)d_in[6];
    const float* Ww = (const float*)d_in[7];
    const float* Wb = (const float*)d_in[8];
    float* out = (float*)d_out;

    cudaFuncSetAttribute(flash_kernel, cudaFuncAttributeMaxDynamicSharedMemorySize, SMB_FLASH);

    conv_mid_kernel<<<dim3(100, 2), 256>>>(b, gw, gb, tw, tb, pw, pb);
    vinit_kernel<<<800, 256>>>();
    build_patches_kernel<<<dim3(3600, 3, 2), 256>>>();
    flash_kernel<<<dim3(67, 2), NTH, SMB_FLASH>>>();
    fold_w_out_kernel<<<dim3(100, 2, 2), 256>>>(Ww, Wb, b, out);
}

// round 17
// speedup vs baseline: 1.1292x; 1.0133x over previous
#include <cuda_runtime.h>
#include <cuda_fp16.h>
#include <cstdint>

#define NLOC 6400
#define DH   144
#define VROWS 160            // 144 dh' + ones row (144) + 15 zero rows
#define NPIX 25600
#define CIN  64
#define CI   16
#define DD   8
#define MIDOFF (4*NPIX)

// ---------------- gmem scratch ----------------
// k-dim permutation: dh' = t*16 + ci  (t = kr*3+kc). Q/K/V/Z all use dh'.
__device__ __half g_Xh[2*3*NPIX*CI];         // conv outputs, [batch][mat][pix][ci], Q pre-scaled
__device__ __half g_Qh[2*NLOC*DH + 32*DH];   // fp16 [l][dh']
__device__ __half g_Kf[2*NLOC*DH];           // fp16 [l][dh']
__device__ __half g_Vt[2*VROWS*NLOC];        // fp16 [dh'][loc], rows 144..159 = ones/zeros
__device__ __half g_Zt[2*NLOC*DH];           // fp16 attention output [l][dh']

// ---------------- helpers ----------------
__device__ __forceinline__ uint32_t smem_u32(const void* p){
    uint32_t a; asm("{ .reg .u64 t; cvta.to.shared.u64 t, %1; cvt.u32.u64 %0, t; }" : "=r"(a) : "l"(p));
    return a;
}
__device__ __forceinline__ float ex2(float x){
    float y; asm("ex2.approx.ftz.f32 %0, %1;" : "=f"(y) : "f"(x)); return y;
}
// pack two fp32 -> fp16x2, lo half = first arg
__device__ __forceinline__ uint32_t pkh(float lo, float hi){
    uint32_t u; asm("cvt.rn.f16x2.f32 %0, %1, %2;" : "=r"(u) : "f"(hi), "f"(lo)); return u;
}
__device__ __forceinline__ uint32_t h2ex2(uint32_t x){
    uint32_t y; asm("ex2.approx.f16x2 %0, %1;" : "=r"(y) : "r"(x)); return y;
}
__device__ __forceinline__ void mma16816(float* d, const uint32_t* a, const uint32_t* b, const float* c){
    asm volatile("mma.sync.aligned.m16n8k16.row.col.f32.f16.f16.f32 "
        "{%0,%1,%2,%3}, {%4,%5,%6,%7}, {%8,%9}, {%10,%11,%12,%13};"
        : "=f"(d[0]),"=f"(d[1]),"=f"(d[2]),"=f"(d[3])
        : "r"(a[0]),"r"(a[1]),"r"(a[2]),"r"(a[3]), "r"(b[0]),"r"(b[1]),
          "f"(c[0]),"f"(c[1]),"f"(c[2]),"f"(c[3]));
}
__device__ __forceinline__ void ldsm4(uint32_t* r, uint32_t addr){
    asm volatile("ldmatrix.sync.aligned.m8n8.x4.shared.b16 {%0,%1,%2,%3}, [%4];"
        : "=r"(r[0]),"=r"(r[1]),"=r"(r[2]),"=r"(r[3]) : "r"(addr));
}
__device__ __forceinline__ void cpa(uint32_t dst, const void* src){
    asm volatile("cp.async.cg.shared.global [%0], [%1], 16;" :: "r"(dst), "l"(src));
}
__device__ __forceinline__ void cp_commit(){ asm volatile("cp.async.commit_group;" ::: "memory"); }
template<int N> __device__ __forceinline__ void cp_wait(){ asm volatile("cp.async.wait_group %0;" :: "n"(N) : "memory"); }

// ================= K1: 1x1 conv at mid slice -> g_Xh [mat][pix][ci] fp16 =========
__global__ void conv_mid_kernel(const float* __restrict__ b,
                                const float* __restrict__ gw, const float* __restrict__ gb,
                                const float* __restrict__ tw, const float* __restrict__ tb,
                                const float* __restrict__ pw, const float* __restrict__ pb)
{
    __shared__ float ws[3*CI*CIN];
    __shared__ float bs[3*CI];
    int tid = threadIdx.x;
    for (int i = tid; i < CI*CIN; i += 256){
        ws[i] = gw[i]; ws[CI*CIN + i] = tw[i]; ws[2*CI*CIN + i] = pw[i];
    }
    if (tid < CI){ bs[tid] = gb[tid]; bs[CI+tid] = tb[tid]; bs[2*CI+tid] = pb[tid]; }
    __syncthreads();

    int pix = blockIdx.x*256 + tid;
    int batch = blockIdx.y;
    const float* bp = b + (size_t)batch*CIN*DD*NPIX + MIDOFF + pix;
    float acc[48];
    #pragma unroll
    for (int i = 0; i < 48; i++) acc[i] = bs[i];
    for (int c = 0; c < CIN; c++){
        float v = bp[(size_t)c*DD*NPIX];
        #pragma unroll
        for (int m = 0; m < 3; m++)
            #pragma unroll
            for (int ci = 0; ci < CI; ci++)
                acc[m*CI + ci] += ws[m*CI*CIN + ci*CIN + c] * v;
    }
    // Q (mat 0) pre-scaled by 10*log2(e)
    #pragma unroll
    for (int ci = 0; ci < CI; ci++) acc[ci] *= 14.4269504088896340736f;

    #pragma unroll
    for (int m = 0; m < 3; m++){
        uint32_t pk[8];
        #pragma unroll
        for (int p = 0; p < 8; p++)
            pk[p] = pkh(acc[m*CI + 2*p], acc[m*CI + 2*p + 1]);
        uint4* dst = (uint4*)(g_Xh + ((size_t)(batch*3 + m)*NPIX + pix)*CI);
        dst[0] = make_uint4(pk[0], pk[1], pk[2], pk[3]);
        dst[1] = make_uint4(pk[4], pk[5], pk[6], pk[7]);
    }
}

// ================= K2a: Q/K patches — pure 32B copy per (l,t) =====================
__global__ void build_qk_kernel()
{
    int idx = blockIdx.x*256 + threadIdx.x;   // 57600 = 225*256
    int mat = blockIdx.y;                     // 0 -> Q (src 0), 1 -> K (src 2)
    int batch = blockIdx.z;
    int l = idx/9, t = idx - l*9;
    int ih = l/80, iw = l - ih*80;
    int kr = t/3, kc = t - kr*3;
    int r = ih*2 + kr - 1, c = iw*2 + kc - 1;
    uint4 v0 = make_uint4(0,0,0,0), v1 = make_uint4(0,0,0,0);
    if ((unsigned)r < 160u && (unsigned)c < 160u){
        const uint4* src = (const uint4*)(g_Xh + ((size_t)(batch*3 + (mat ? 2 : 0))*NPIX + r*160 + c)*CI);
        v0 = src[0]; v1 = src[1];
    }
    uint4* dst = (uint4*)((mat ? g_Kf : g_Qh) + (size_t)batch*NLOC*DH + (size_t)l*DH + t*16);
    dst[0] = v0; dst[1] = v1;
}

// ================= K2b: V patches transposed [dh'][loc] + ones/zero rows =========
#define VSP 136
__global__ void build_v_kernel()
{
    __shared__ __half vs[144*VSP];
    int tid = threadIdx.x;
    int l0 = blockIdx.x*128;
    int batch = blockIdx.y;

    #pragma unroll
    for (int j = 0; j < 5; j++){
        int id = tid + j*256;                 // 1152 tasks = 128 l x 9 t
        if (id < 1152){
            int ll = id/9, t = id - ll*9;
            int l = l0 + ll;
            int ih = l/80, iw = l - ih*80;
            int kr = t/3, kc = t - kr*3;
            int r = ih*2 + kr - 1, c = iw*2 + kc - 1;
            if ((unsigned)r < 160u && (unsigned)c < 160u){
                const uint4* src = (const uint4*)(g_Xh + ((size_t)(batch*3 + 1)*NPIX + r*160 + c)*CI);
                uint4 v0 = src[0], v1 = src[1];
                const __half* hv0 = (const __half*)&v0;
                const __half* hv1 = (const __half*)&v1;
                #pragma unroll
                for (int ci = 0; ci < 8; ci++){
                    vs[(t*16+ci)*VSP + ll]   = hv0[ci];
                    vs[(t*16+8+ci)*VSP + ll] = hv1[ci];
                }
            } else {
                #pragma unroll
                for (int ci = 0; ci < 16; ci++)
                    vs[(t*16+ci)*VSP + ll] = __float2half(0.f);
            }
        }
    }
    __syncthreads();

    if (tid < 160){
        __half* dst = g_Vt + (size_t)batch*VROWS*NLOC + (size_t)tid*NLOC + l0;
        if (tid < 144){
            uint4* d4 = (uint4*)dst;
            const uint4* s4 = (const uint4*)(vs + tid*VSP);
            #pragma unroll
            for (int k = 0; k < 16; k++) d4[k] = s4[k];
        } else {
            __half hv = (tid == 144) ? __float2half(1.f) : __float2half(0.f);
            #pragma unroll
            for (int k = 0; k < 128; k++) dst[k] = hv;
        }
    }
}

// ================= K3: flash attention, mma.sync (HMMA), 12 warps/key-split ======
#define BM   96
#define KSTR 152              // halves per K-tile row (304B, conflict-free ldsm)
#define VSTR 72               // halves per V-tile row (144B)
#define KTB  (64*KSTR*2)      // 19456 bytes
#define VTB  (VROWS*VSTR*2)   // 23040 bytes
#define BUFB (KTB+VTB)        // 42496
#define SMB_FLASH (4*BUFB)    // 169984
#define NTH  384

__device__ __forceinline__ void load_tiles(uint32_t smb, int buf,
                                           const __half* Kg, const __half* Vg,
                                           int kb, int tid)
{
    uint32_t kd = smb + buf*BUFB;
    const __half* ks = Kg + (size_t)kb*64*DH;
    #pragma unroll
    for (int j = 0; j < 3; j++){
        int id = tid + j*NTH;             // 64 rows x 18 chunks(16B) = 1152
        int r = id/18, c = id - r*18;
        cpa(kd + r*(KSTR*2) + c*16, ks + r*DH + c*8);
    }
    uint32_t vd = smb + buf*BUFB + KTB;
    const __half* vs = Vg + kb*64;
    #pragma unroll
    for (int j = 0; j < 4; j++){
        int id = tid + j*NTH;             // 160 rows x 8 chunks(16B) = 1280
        if (id < 1280){
            int r = id>>3, c = id&7;
            cpa(vd + r*(VSTR*2) + c*16, vs + (size_t)r*NLOC + c*8);
        }
    }
}

__global__ __launch_bounds__(NTH, 1) void flash_kernel()
{
    extern __shared__ char sm[];
    uint32_t smb = smem_u32(sm);
    const int tid = threadIdx.x, w = tid>>5, lane = tid&31;
    const int g = lane>>2, tig = lane&3;
    const int wp = w>>1;                 // row group 0..5
    const int hf = w&1;                  // key half 0/1
    const int qb = blockIdx.x, batch = blockIdx.y;

    const __half* Qg = g_Qh + (size_t)batch*NLOC*DH;
    const __half* Kg = g_Kf + (size_t)batch*NLOC*DH;
    const __half* Vg = g_Vt + (size_t)batch*VROWS*NLOC;

    // ---- Q fragments (fp16 direct), rows row0 and row0+8 ----
    const int row0 = qb*BM + wp*16 + g;
    const int r0c = min(row0, NLOC-1), r1c = min(row0+8, NLOC-1);
    uint32_t qh[36];
    #pragma unroll
    for (int t = 0; t < 9; t++){
        const __half* p0 = Qg + (size_t)r0c*DH + t*16 + tig*2;
        const __half* p1 = Qg + (size_t)r1c*DH + t*16 + tig*2;
        qh[4*t+0] = *(const uint32_t*)p0;
        qh[4*t+1] = *(const uint32_t*)p1;
        qh[4*t+2] = *(const uint32_t*)(p0 + 8);
        qh[4*t+3] = *(const uint32_t*)(p1 + 8);
    }

    // ldmatrix per-lane base offsets
    const int lm = lane>>3;
    const int lr = lane&7;
    const int lrow = lr + ((lm&2)<<2);
    const int lcol = (lm&1)*16;

    // oa[0..17]: O (144 dh'). oa[18]: l column (col 144 live). Partial over key half.
    float oa[19][4];
    #pragma unroll
    for (int j = 0; j < 19; j++){ oa[j][0]=0.f; oa[j][1]=0.f; oa[j][2]=0.f; oa[j][3]=0.f; }
    float m0 = -1e30f, m1 = -1e30f;     // per-warp running max over OWN key half

    load_tiles(smb, 0, Kg, Vg, 0, tid); cp_commit();
    load_tiles(smb, 1, Kg, Vg, 1, tid); cp_commit();

    for (int tt = 0; tt < 50; tt++){
        __syncthreads();
        if (tt < 49){
            load_tiles(smb, (2*tt+2)&3, Kg, Vg, 2*tt+2, tid); cp_commit();
            load_tiles(smb, (2*tt+3)&3, Kg, Vg, 2*tt+3, tid); cp_commit();
            cp_wait<2>();
        } else {
            cp_wait<0>();
        }

        #pragma unroll
        for (int u = 0; u < 2; u++){
            const int t = 2*tt + u;
            const uint32_t kmb = smb + (t&3)*BUFB + (hf*32 + lrow)*(KSTR*2) + lcol;
            const uint32_t vmb = smb + (t&3)*BUFB + KTB + lrow*(VSTR*2) + lcol + hf*64;

            // ---- S = Q*K over this warp's 32 keys ----
            float sa[4][4];
            #pragma unroll
            for (int j = 0; j < 4; j++){ sa[j][0]=0.f; sa[j][1]=0.f; sa[j][2]=0.f; sa[j][3]=0.f; }
            #pragma unroll
            for (int kt = 0; kt < 9; kt++){
                uint32_t bb[2][4];
                ldsm4(bb[0], kmb + kt*32);
                ldsm4(bb[1], kmb + 16*(KSTR*2) + kt*32);
                mma16816(sa[0], &qh[4*kt], bb[0],   sa[0]);
                mma16816(sa[1], &qh[4*kt], bb[0]+2, sa[1]);
                mma16816(sa[2], &qh[4*kt], bb[1],   sa[2]);
                mma16816(sa[3], &qh[4*kt], bb[1]+2, sa[3]);
            }

            // ---- local max (per-warp, independent) ----
            float mx0 = fmaxf(fmaxf(sa[0][0], sa[0][1]), fmaxf(sa[1][0], sa[1][1]));
            float mx1 = fmaxf(fmaxf(sa[0][2], sa[0][3]), fmaxf(sa[1][2], sa[1][3]));
            mx0 = fmaxf(mx0, fmaxf(fmaxf(sa[2][0], sa[2][1]), fmaxf(sa[3][0], sa[3][1])));
            mx1 = fmaxf(mx1, fmaxf(fmaxf(sa[2][2], sa[2][3]), fmaxf(sa[3][2], sa[3][3])));

            if (!__all_sync(0xffffffffu, (mx0 <= m0) && (mx1 <= m1))){
                mx0 = fmaxf(mx0, __shfl_xor_sync(0xffffffffu, mx0, 1));
                mx0 = fmaxf(mx0, __shfl_xor_sync(0xffffffffu, mx0, 2));
                mx1 = fmaxf(mx1, __shfl_xor_sync(0xffffffffu, mx1, 1));
                mx1 = fmaxf(mx1, __shfl_xor_sync(0xffffffffu, mx1, 2));
                float m0n = fmaxf(m0, mx0), m1n = fmaxf(m1, mx1);
                float sc0 = ex2(m0 - m0n),  sc1 = ex2(m1 - m1n);
                m0 = m0n; m1 = m1n;
                #pragma unroll
                for (int j = 0; j < 19; j++){
                    oa[j][0] *= sc0; oa[j][1] *= sc0;
                    oa[j][2] *= sc1; oa[j][3] *= sc1;
                }
            }

            // ---- P fragments via fp16x2 exp2 ----
            uint32_t pa[2][4];
            #pragma unroll
            for (int k2 = 0; k2 < 2; k2++){
                pa[k2][0] = h2ex2(pkh(sa[2*k2][0]  - m0, sa[2*k2][1]  - m0));
                pa[k2][1] = h2ex2(pkh(sa[2*k2][2]  - m1, sa[2*k2][3]  - m1));
                pa[k2][2] = h2ex2(pkh(sa[2*k2+1][0]- m0, sa[2*k2+1][1]- m0));
                pa[k2][3] = h2ex2(pkh(sa[2*k2+1][2]- m1, sa[2*k2+1][3]- m1));
            }

            // ---- O += P * V over this warp's 32 keys (9 dh' blocks + l block) ----
            #pragma unroll
            for (int k2 = 0; k2 < 2; k2++){
                #pragma unroll
                for (int np = 0; np < 9; np++){
                    uint32_t bb[4];
                    ldsm4(bb, vmb + np*16*(VSTR*2) + k2*32);
                    mma16816(oa[2*np],   pa[k2], bb,   oa[2*np]);
                    mma16816(oa[2*np+1], pa[k2], bb+2, oa[2*np+1]);
                }
                uint32_t bb[4];
                ldsm4(bb, vmb + 9*16*(VSTR*2) + k2*32);
                mma16816(oa[18], pa[k2], bb, oa[18]);
            }
        }
    }

    // ================= merge warp pairs (odd -> smem, even combines) =============
    __syncthreads();                      // tile reads done; reuse smem
    float4* xO = (float4*)sm;             // [6 wp][32 lanes][20 f4]
    float*  xM = (float*)(sm + 61440);    // [6 wp][32 lanes][2]
    if (hf){
        float4* dst = xO + (size_t)wp*640 + lane*20;
        #pragma unroll
        for (int j = 0; j < 19; j++)
            dst[j] = make_float4(oa[j][0], oa[j][1], oa[j][2], oa[j][3]);
        float* mm = xM + wp*64 + lane*2;
        mm[0] = m0; mm[1] = m1;
    }
    __syncthreads();
    if (!hf){
        const float4* src = xO + (size_t)wp*640 + lane*20;
        const float* mm = xM + wp*64 + lane*2;
        float pm0 = mm[0], pm1 = mm[1];
        float ms0 = fmaxf(m0, pm0), ms1 = fmaxf(m1, pm1);
        float sA0 = ex2(m0 - ms0), sB0 = ex2(pm0 - ms0);
        float sA1 = ex2(m1 - ms1), sB1 = ex2(pm1 - ms1);
        #pragma unroll
        for (int j = 0; j < 19; j++){
            float4 p = src[j];
            oa[j][0] = oa[j][0]*sA0 + p.x*sB0;
            oa[j][1] = oa[j][1]*sA0 + p.y*sB0;
            oa[j][2] = oa[j][2]*sA1 + p.z*sB1;
            oa[j][3] = oa[j][3]*sA1 + p.w*sB1;
        }
        float l0 = __shfl_sync(0xffffffffu, oa[18][0], lane & 28);
        float l1 = __shfl_sync(0xffffffffu, oa[18][2], lane & 28);
        float i0 = 1.f/l0, i1 = 1.f/l1;

        // O columns are already in dh' order: write Zt directly
        __half* Zt = g_Zt + (size_t)batch*NLOC*DH;
        if (row0 < NLOC){
            __half* z = Zt + (size_t)row0*DH + tig*2;
            #pragma unroll
            for (int j = 0; j < 18; j++)
                *(uint32_t*)(z + j*8) = pkh(oa[j][0]*i0, oa[j][1]*i0);
        }
        if (row0 + 8 < NLOC){
            __half* z = Zt + (size_t)(row0+8)*DH + tig*2;
            #pragma unroll
            for (int j = 0; j < 18; j++)
                *(uint32_t*)(z + j*8) = pkh(oa[j][2]*i1, oa[j][3]*i1);
        }
    }
}

// ================= K4: fused fold + W conv + residual add (c-half split) =========
__global__ void fold_w_out_kernel(const float* __restrict__ Ww, const float* __restrict__ Wb,
                                  const float* __restrict__ bin, float* __restrict__ out)
{
    __shared__ float ws[32*CI];
    __shared__ float wb[32];
    int tid = threadIdx.x;
    int c0 = blockIdx.z*32;
    for (int i = tid; i < 32*CI; i += 256) ws[i] = Ww[c0*CI + i];
    if (tid < 32) wb[tid] = Wb[c0 + tid];
    __syncthreads();

    int pix = blockIdx.x*256 + tid;
    int batch = blockIdx.y;
    int h = pix / 160, w = pix % 160;

    int krs[2], ihs[2], nr = 0;
    if (!(h & 1)){ krs[0] = 1; ihs[0] = h >> 1; nr = 1; }
    else { if (h < 159){ krs[nr] = 0; ihs[nr] = (h+1) >> 1; nr++; } krs[nr] = 2; ihs[nr] = (h-1) >> 1; nr++; }
    int kcs[2], iws[2], nc = 0;
    if (!(w & 1)){ kcs[0] = 1; iws[0] = w >> 1; nc = 1; }
    else { if (w < 159){ kcs[nc] = 0; iws[nc] = (w+1) >> 1; nc++; } kcs[nc] = 2; iws[nc] = (w-1) >> 1; nc++; }

    const __half* Z = g_Zt + (size_t)batch*NLOC*DH;
    float acc[CI];
    #pragma unroll
    for (int ci = 0; ci < CI; ci++) acc[ci] = 0.f;
    for (int a = 0; a < nr; a++)
        for (int bb = 0; bb < nc; bb++){
            int l = ihs[a]*80 + iws[bb];
            const uint4* zp = (const uint4*)(Z + (size_t)l*DH + (krs[a]*3 + kcs[bb])*16);
            uint4 v0 = zp[0], v1 = zp[1];
            const __half2* h0 = (const __half2*)&v0;
            const __half2* h1 = (const __half2*)&v1;
            #pragma unroll
            for (int p = 0; p < 4; p++){
                float2 f0 = __half22float2(h0[p]);
                float2 f1 = __half22float2(h1[p]);
                acc[2*p+0] += f0.x; acc[2*p+1] += f0.y;
                acc[8+2*p+0] += f1.x; acc[8+2*p+1] += f1.y;
            }
        }
    float inv = 1.f / (float)(nr*nc);
    #pragma unroll
    for (int ci = 0; ci < CI; ci++) acc[ci] *= inv;

    const float* bp = bin + (size_t)batch*CIN*DD*NPIX + (size_t)c0*DD*NPIX + pix;
    float*       op = out + (size_t)batch*CIN*DD*NPIX + (size_t)c0*DD*NPIX + pix;
    #pragma unroll 2
    for (int c = 0; c < 32; c++){
        float y = wb[c];
        #pragma unroll
        for (int ci = 0; ci < CI; ci++) y += ws[c*CI + ci]*acc[ci];
        const float* bc = bp + (size_t)c*DD*NPIX;
        float*       oc = op + (size_t)c*DD*NPIX;
        #pragma unroll
        for (int d = 0; d < DD; d++)
            oc[(size_t)d*NPIX] = bc[(size_t)d*NPIX] + y;
    }
}

// ================= launch =================
extern "C" void kernel_launch(void* const* d_in, const int* in_sizes, int n_in,
                              void* d_out, int out_size)
{
    const float* b  = (const float*)d_in[0];
    const float* gw = (const float*)d_in[1];
    const float* gb = (const float*)d_in[2];
    const float* tw = (const float*)d_in[3];
    const float* tb = (const float*)d_in[4];
    const float* pw = (const float*)d_in[5];
    const float* pb = (const float*)d_in[6];
    const float* Ww = (const float*)d_in[7];
    const float* Wb = (const float*)d_in[8];
    float* out = (float*)d_out;

    cudaFuncSetAttribute(flash_kernel, cudaFuncAttributeMaxDynamicSharedMemorySize, SMB_FLASH);

    conv_mid_kernel<<<dim3(100, 2), 256>>>(b, gw, gb, tw, tb, pw, pb);
    build_qk_kernel<<<dim3(225, 2, 2), 256>>>();
    build_v_kernel<<<dim3(50, 2), 256>>>();
    flash_kernel<<<dim3(67, 2), NTH, SMB_FLASH>>>();
    fold_w_out_kernel<<<dim3(100, 2, 2), 256>>>(Ww, Wb, b, out);
}